// round 11
// baseline (speedup 1.0000x reference)
#include <cuda_runtime.h>
#include <math.h>

#define SS 128
#define BB 32
#define VV 32000
#define NINP 1024
#define NHID 1024
#define NHEADS 16
#define HD 64
#define KSPLIT 8

// ---------------- device scratch ----------------
static __device__ float g_emb[(size_t)SS * BB * NINP];       // raw fp32 embeddings
static __device__ float g_xbuf[BB * 3072];                   // [hidden|q|attn] fp32
static __device__ float g_kcache[(size_t)(SS + 1) * BB * NHID];
static __device__ float g_vcache[(size_t)(SS + 1) * BB * NHID];
static __device__ float g_inter[BB * 4096];
static __device__ float g_part[KSPLIT * BB * 4096];          // split-K partials
// decoder blobs: bf16 hi/lo smem images. W chunk = 4608 words = 1152 uint4;
// A chunk = 9216 words = 2304 uint4.
static __device__ uint4 g_wd[(size_t)500 * 16 * 1152];       // dec_w [32000][1024]
static __device__ uint4 g_aimg[(size_t)32 * 16 * 2304];      // states rows (32 mb x 16 gc)

// ---------------- helpers ----------------
__device__ __forceinline__ unsigned packbf(float e, float o) {
    // word = {lo16 = bf16(e), hi16 = bf16(o)}
    unsigned r;
    asm("cvt.rn.bf16x2.f32 %0, %1, %2;" : "=r"(r) : "f"(o), "f"(e));
    return r;
}
__device__ __forceinline__ void splitpair(float v0, float v1, unsigned& h, unsigned& l) {
    h = packbf(v0, v1);
    float r0 = v0 - __uint_as_float(h << 16);
    float r1 = v1 - __uint_as_float(h & 0xffff0000u);
    l = packbf(r0, r1);
}
__device__ __forceinline__ void cvtpair(float4 v, unsigned* ph, unsigned* pl) {
    unsigned h0 = packbf(v.x, v.y);
    unsigned h1 = packbf(v.z, v.w);
    float r0 = v.x - __uint_as_float(h0 << 16);
    float r1 = v.y - __uint_as_float(h0 & 0xffff0000u);
    float r2 = v.z - __uint_as_float(h1 << 16);
    float r3 = v.w - __uint_as_float(h1 & 0xffff0000u);
    ph[0] = h0; ph[1] = h1;
    pl[0] = packbf(r0, r1);
    pl[1] = packbf(r2, r3);
}
__device__ __forceinline__ void mmabf(float* c, unsigned a0, unsigned a1, unsigned a2,
                                      unsigned a3, unsigned b0, unsigned b1) {
    asm volatile(
        "mma.sync.aligned.m16n8k16.row.col.f32.bf16.bf16.f32 "
        "{%0,%1,%2,%3},{%4,%5,%6,%7},{%8,%9},{%0,%1,%2,%3};"
        : "+f"(c[0]), "+f"(c[1]), "+f"(c[2]), "+f"(c[3])
        : "r"(a0), "r"(a1), "r"(a2), "r"(a3), "r"(b0), "r"(b1));
}
__device__ __forceinline__ void cp_commit() { asm volatile("cp.async.commit_group;"); }
template <int N>
__device__ __forceinline__ void cp_wait() { asm volatile("cp.async.wait_group %0;" ::"n"(N)); }
#define CPA16(d, s) asm volatile("cp.async.cg.shared.global [%0], [%1], 16;" ::"r"(d), "l"(s))

// ---------------- one-time dec_w conversion into blob layout ----------------
__global__ void k_cvt_w(const float* __restrict__ src, unsigned* __restrict__ dst,
                        int N, int K) {
    long total = (long)N * (K >> 1);
    long stride = (long)gridDim.x * blockDim.x;
    int KC = K >> 6;
    for (long i = (long)blockIdx.x * blockDim.x + threadIdx.x; i < total; i += stride) {
        int n = (int)(i / (K >> 1));
        int kw = (int)(i - (long)n * (K >> 1));
        float2 v = *(const float2*)(src + (size_t)n * K + 2 * kw);
        unsigned h, l;
        splitpair(v.x, v.y, h, l);
        int nt = n >> 6, r = n & 63, gc = kw >> 5, w = kw & 31;
        size_t base = ((size_t)nt * KC + gc) * 4608;   // words
        dst[base + r * 36 + w] = h;
        dst[base + 2304 + r * 36 + w] = l;
    }
}

// ---------------- setup (round-4 verbatim) ----------------
__global__ void k_init(const float* __restrict__ h0, const float* __restrict__ kc0,
                       const float* __restrict__ vc0, float* __restrict__ states_full) {
    int b = blockIdx.x, t = threadIdx.x;
    float4 h = ((const float4*)(h0 + b * NHID))[t];
    ((float4*)(g_xbuf + b * 3072))[t] = h;
    ((float4*)(states_full + (size_t)b * NHID))[t] = h;
    ((float4*)(g_kcache + (size_t)b * NHID))[t] = ((const float4*)(kc0 + b * NHID))[t];
    ((float4*)(g_vcache + (size_t)b * NHID))[t] = ((const float4*)(vc0 + b * NHID))[t];
}

__global__ void k_embed(const int* __restrict__ obs, const float* __restrict__ enc_w) {
    int idx = blockIdx.x;  // s*B + b
    int row = obs[idx];
    ((float4*)(g_emb + (size_t)idx * NINP))[threadIdx.x] =
        ((const float4*)(enc_w + (size_t)row * NINP))[threadIdx.x];
}

// ---------------- step GEMM (round-4 VERBATIM) ----------------
__global__ __launch_bounds__(256) void k_gemm_step(int estep, int xsel,
                                                   const float* __restrict__ W,
                                                   int K, int klen, int N, int permute) {
    __shared__ unsigned xh[32][36], xl[32][36], wh[64][36], wl[64][36];
    const int tid = threadIdx.x;
    const int nb = blockIdx.x * 64;
    const int k0 = blockIdx.y * klen;
    const int w = tid >> 5, lane = tid & 31, g = lane >> 2, tig = lane & 3;

    const float* xe = g_emb + (size_t)(estep > 0 ? estep : 0) * BB * NINP;
    const int ecols = (estep >= 0) ? NINP : 0;
    const float* xr = xsel ? g_inter : g_xbuf;
    const int xstride = xsel ? 4096 : 3072;

    float acc[2][4] = {};
    float4 xa[2], wa[4];

    auto loadx = [&](int kc) {
#pragma unroll
        for (int i = 0; i < 2; i++) {
            int e = tid + i * 256;
            int r = e >> 4, cg = (e & 15) << 2;
            int gc = kc + cg;
            const float* src = (gc < ecols) ? (xe + r * NINP + gc)
                                            : (xr + r * xstride + (gc - ecols));
            xa[i] = *(const float4*)src;
        }
#pragma unroll
        for (int i = 0; i < 4; i++) {
            int e = tid + i * 256;
            int r = e >> 4, cg = (e & 15) << 2;
            int gc = kc + cg;
            int wc = gc;
            if (permute) wc = (gc < 1024) ? gc : ((gc < 2048) ? gc + 2048 : gc - 1024);
            wa[i] = *(const float4*)(W + (size_t)(nb + r) * K + wc);
        }
    };
    auto store = [&]() {
#pragma unroll
        for (int i = 0; i < 2; i++) {
            int e = tid + i * 256;
            int r = e >> 4, wd = (e & 15) * 2;
            cvtpair(xa[i], &xh[r][wd], &xl[r][wd]);
        }
#pragma unroll
        for (int i = 0; i < 4; i++) {
            int e = tid + i * 256;
            int r = e >> 4, wd = (e & 15) * 2;
            cvtpair(wa[i], &wh[r][wd], &wl[r][wd]);
        }
    };

    const int nchunks = klen >> 6;
    loadx(k0);
    for (int c = 0; c < nchunks; c++) {
        store();
        __syncthreads();
        if (c + 1 < nchunks) loadx(k0 + (c + 1) * 64);
#pragma unroll
        for (int s = 0; s < 4; s++) {
            int w0 = s * 8 + tig, w1 = w0 + 4;
            unsigned bh0 = wh[w * 8 + g][w0], bh1 = wh[w * 8 + g][w1];
            unsigned bl0 = wl[w * 8 + g][w0], bl1 = wl[w * 8 + g][w1];
#pragma unroll
            for (int mt = 0; mt < 2; mt++) {
                int r0 = mt * 16 + g;
                unsigned ah0 = xh[r0][w0], ah1 = xh[r0 + 8][w0];
                unsigned ah2 = xh[r0][w1], ah3 = xh[r0 + 8][w1];
                unsigned al0 = xl[r0][w0], al1 = xl[r0 + 8][w0];
                unsigned al2 = xl[r0][w1], al3 = xl[r0 + 8][w1];
                mmabf(acc[mt], ah0, ah1, ah2, ah3, bh0, bh1);
                mmabf(acc[mt], ah0, ah1, ah2, ah3, bl0, bl1);
                mmabf(acc[mt], al0, al1, al2, al3, bh0, bh1);
            }
        }
        __syncthreads();
    }
    float* p = g_part + (size_t)blockIdx.y * 32 * N;
    int n0 = nb + w * 8 + 2 * tig;
#pragma unroll
    for (int mt = 0; mt < 2; mt++) {
        int r0 = mt * 16 + g;
        *(float2*)&p[r0 * N + n0] = make_float2(acc[mt][0], acc[mt][1]);
        *(float2*)&p[(r0 + 8) * N + n0] = make_float2(acc[mt][2], acc[mt][3]);
    }
}

// ---------------- fused LN(q)+relu + attention (round-6 VERBATIM) ----------------
__global__ __launch_bounds__(512) void k_lnq_attn(const float* __restrict__ qb,
                                                  const float* __restrict__ gg,
                                                  const float* __restrict__ bbv, int step) {
    __shared__ float q[1024];
    __shared__ float sc[NHEADS][132];
    __shared__ float r1[16], r2[16];
    int b = blockIdx.x, tid = threadIdx.x, lane = tid & 31, wid = tid >> 5;

    float2 v = *(const float2*)(qb + 2 * tid);
#pragma unroll
    for (int j = 0; j < KSPLIT; j++) {
        float2 p = *(const float2*)(g_part + (size_t)j * 32 * 1024 + b * 1024 + 2 * tid);
        v.x += p.x; v.y += p.y;
    }
    float s1 = v.x + v.y, s2 = v.x * v.x + v.y * v.y;
#pragma unroll
    for (int o = 16; o; o >>= 1) {
        s1 += __shfl_xor_sync(0xffffffffu, s1, o);
        s2 += __shfl_xor_sync(0xffffffffu, s2, o);
    }
    if (lane == 0) { r1[wid] = s1; r2[wid] = s2; }
    __syncthreads();
    s1 = 0.f; s2 = 0.f;
#pragma unroll
    for (int i = 0; i < 16; i++) { s1 += r1[i]; s2 += r2[i]; }
    float mu = s1 * (1.f / 1024.f);
    float rstd = rsqrtf(s2 * (1.f / 1024.f) - mu * mu + 1e-5f);
    float q0 = fmaxf((v.x - mu) * rstd * gg[2 * tid] + bbv[2 * tid], 0.f);
    float q1 = fmaxf((v.y - mu) * rstd * gg[2 * tid + 1] + bbv[2 * tid + 1], 0.f);
    q[2 * tid] = q0;
    q[2 * tid + 1] = q1;
    *(float2*)&g_xbuf[b * 3072 + 1024 + 2 * tid] = make_float2(q0, q1);
    __syncthreads();

    const int hh = wid;
    const int L = step + 1;
    const float* qh = q + hh * HD;
    float msc[4], m = -1e30f;
#pragma unroll
    for (int i = 0; i < 4; i++) {
        int c = lane + i * 32;
        float d = -1e30f;
        if (c < L) {
            const float* kr = g_kcache + ((size_t)c * BB + b) * NHID + hh * HD;
            float acc = 0.f;
#pragma unroll
            for (int j = 0; j < 16; j++) {
                float4 kv = *(const float4*)&kr[j * 4];
                acc += qh[j * 4] * kv.x + qh[j * 4 + 1] * kv.y +
                       qh[j * 4 + 2] * kv.z + qh[j * 4 + 3] * kv.w;
            }
            d = acc * 0.125f;
        }
        msc[i] = d;
        m = fmaxf(m, d);
    }
#pragma unroll
    for (int o = 16; o; o >>= 1) m = fmaxf(m, __shfl_xor_sync(0xffffffffu, m, o));
    float se = 0.f;
#pragma unroll
    for (int i = 0; i < 4; i++) {
        float e = expf(msc[i] - m);   // c >= L -> exp(-huge) = 0
        sc[hh][lane + i * 32] = e;
        se += e;
    }
#pragma unroll
    for (int o = 16; o; o >>= 1) se += __shfl_xor_sync(0xffffffffu, se, o);
    float inv = 1.f / se;
    __syncwarp();

    float o0 = 0.f, o1 = 0.f;
    const float* vbase = g_vcache + (size_t)b * NHID + hh * HD + 2 * lane;
#pragma unroll 4
    for (int c = 0; c < L; c++) {
        float wgt = sc[hh][c];
        float2 vv = *(const float2*)(vbase + (size_t)c * BB * NHID);
        o0 += wgt * vv.x;
        o1 += wgt * vv.y;
    }
    *(float2*)&g_xbuf[b * 3072 + 2048 + hh * HD + 2 * lane] = make_float2(o0 * inv, o1 * inv);
}

// ---------------- LN(int)+relu -> g_inter (round-4 verbatim) ----------------
__global__ __launch_bounds__(256) void k_ln_int(const float* __restrict__ bias,
                                                const float* __restrict__ gg,
                                                const float* __restrict__ bb2) {
    __shared__ float pre[4096];
    __shared__ float red1[8], red2[8];
    int b = blockIdx.x, tid = threadIdx.x, lane = tid & 31, wid = tid >> 5;
    float s1 = 0.f, s2 = 0.f;
#pragma unroll
    for (int i = 0; i < 4; i++) {
        int c = (tid + i * 256) * 4;
        float4 v = *(const float4*)&bias[c];
#pragma unroll
        for (int j = 0; j < KSPLIT; j++) {
            float4 p = *(const float4*)&g_part[(size_t)j * 32 * 4096 + b * 4096 + c];
            v.x += p.x; v.y += p.y; v.z += p.z; v.w += p.w;
        }
        *(float4*)&pre[c] = v;
        s1 += v.x + v.y + v.z + v.w;
        s2 += v.x * v.x + v.y * v.y + v.z * v.z + v.w * v.w;
    }
#pragma unroll
    for (int o = 16; o; o >>= 1) {
        s1 += __shfl_xor_sync(0xffffffffu, s1, o);
        s2 += __shfl_xor_sync(0xffffffffu, s2, o);
    }
    if (lane == 0) { red1[wid] = s1; red2[wid] = s2; }
    __syncthreads();
    s1 = 0.f; s2 = 0.f;
#pragma unroll
    for (int i = 0; i < 8; i++) { s1 += red1[i]; s2 += red2[i]; }
    float mu = s1 * (1.f / 4096.f);
    float rstd = rsqrtf(s2 * (1.f / 4096.f) - mu * mu + 1e-5f);
#pragma unroll
    for (int i = 0; i < 16; i++) {
        int c = tid + i * 256;
        g_inter[b * 4096 + c] = fmaxf((pre[c] - mu) * rstd * gg[c] + bb2[c], 0.f);
    }
}

// ---------------- LN(fin)+relu -> caches/states/hidden + decoder-A blob ----------------
__global__ __launch_bounds__(256) void k_ln_fin(const float* __restrict__ bias,
                                                const float* __restrict__ gg,
                                                const float* __restrict__ bb2, int step,
                                                float* __restrict__ states_full) {
    __shared__ float pre[3072];
    __shared__ float red1[8], red2[8];
    int b = blockIdx.x, tid = threadIdx.x, lane = tid & 31, wid = tid >> 5;
    float s1 = 0.f, s2 = 0.f;
#pragma unroll
    for (int i = 0; i < 3; i++) {
        int c = (tid + i * 256) * 4;
        float4 v = *(const float4*)&bias[c];
#pragma unroll
        for (int j = 0; j < KSPLIT; j++) {
            float4 p = *(const float4*)&g_part[(size_t)j * 32 * 3072 + b * 3072 + c];
            v.x += p.x; v.y += p.y; v.z += p.z; v.w += p.w;
        }
        *(float4*)&pre[c] = v;
        s1 += v.x + v.y + v.z + v.w;
        s2 += v.x * v.x + v.y * v.y + v.z * v.z + v.w * v.w;
    }
#pragma unroll
    for (int o = 16; o; o >>= 1) {
        s1 += __shfl_xor_sync(0xffffffffu, s1, o);
        s2 += __shfl_xor_sync(0xffffffffu, s2, o);
    }
    if (lane == 0) { red1[wid] = s1; red2[wid] = s2; }
    __syncthreads();
    s1 = 0.f; s2 = 0.f;
#pragma unroll
    for (int i = 0; i < 8; i++) { s1 += red1[i]; s2 += red2[i]; }
    float mu = s1 * (1.f / 3072.f);
    float rstd = rsqrtf(s2 * (1.f / 3072.f) - mu * mu + 1e-5f);
#pragma unroll
    for (int i = 0; i < 6; i++) {
        int c2 = 2 * (tid + i * 256);
        float y0 = fmaxf((pre[c2] - mu) * rstd * gg[c2] + bb2[c2], 0.f);
        float y1 = fmaxf((pre[c2 + 1] - mu) * rstd * gg[c2 + 1] + bb2[c2 + 1], 0.f);
        if (c2 < 1024) {
            *(float2*)&g_kcache[((size_t)(step + 1) * BB + b) * NHID + c2] = make_float2(y0, y1);
        } else if (c2 < 2048) {
            *(float2*)&g_vcache[((size_t)(step + 1) * BB + b) * NHID + (c2 - 1024)] =
                make_float2(y0, y1);
        } else {
            int d = c2 - 2048;
            *(float2*)&states_full[((size_t)(step + 1) * BB + b) * NHID + d] = make_float2(y0, y1);
            *(float2*)&g_xbuf[b * 3072 + d] = make_float2(y0, y1);
            unsigned h_, l_;
            splitpair(y0, y1, h_, l_);
            int ar = step * 32 + b;
            unsigned* a = (unsigned*)g_aimg + ((size_t)((ar >> 7) * 16 + (d >> 6))) * 9216 +
                          (ar & 127) * 36 + ((d & 63) >> 1);
            a[0] = h_;
            a[4608] = l_;
        }
    }
}

// ---------------- decoder: 128m x 64n tiles, cp.async blobs (round-10 verbatim) ----------
__global__ __launch_bounds__(256, 2) void k_dec(const float* __restrict__ bias,
                                                float* __restrict__ out) {
    extern __shared__ uint4 dsm[];
    unsigned sb = (unsigned)__cvta_generic_to_shared(dsm);
    const int tid = threadIdx.x;
    const int mb = blockIdx.x, nbk = blockIdx.y;
    const int w = tid >> 5, lane = tid & 31, g = lane >> 2, tig = lane & 3;
    const int mw = w >> 1, nw = w & 1;
    float acc[2][4][4] = {};

    auto issue = [&](int stage, int gc) {
        const uint4* asrc = g_aimg + ((size_t)(mb * 16 + gc)) * 2304;
        const uint4* wsrc = g_wd + ((size_t)(nbk * 16 + gc)) * 1152;
        unsigned db = sb + stage * 55296;
        for (int u = tid; u < 3456; u += 256) {
            const uint4* s_ = (u < 2304) ? (asrc + u) : (wsrc + (u - 2304));
            CPA16(db + u * 16, s_);
        }
        cp_commit();
    };

    issue(0, 0);
    issue(1, 1);
    for (int cc = 0; cc < 16; cc++) {
        cp_wait<1>();
        __syncthreads();
        const unsigned* st = (const unsigned*)dsm + (cc & 1) * 13824;
        const unsigned* ah = st;
        const unsigned* al = st + 4608;
        const unsigned* wh = st + 9216;
        const unsigned* wl = st + 11520;
#pragma unroll
        for (int s = 0; s < 4; s++) {
            int w0 = s * 8 + tig, w1 = w0 + 4;
            unsigned bh[4][2], bl[4][2];
#pragma unroll
            for (int nt = 0; nt < 4; nt++) {
                int col = nw * 32 + nt * 8 + g;
                bh[nt][0] = wh[col * 36 + w0];
                bh[nt][1] = wh[col * 36 + w1];
                bl[nt][0] = wl[col * 36 + w0];
                bl[nt][1] = wl[col * 36 + w1];
            }
#pragma unroll
            for (int mt = 0; mt < 2; mt++) {
                int r0 = mw * 32 + mt * 16 + g;
                unsigned a0 = ah[r0 * 36 + w0], a1 = ah[(r0 + 8) * 36 + w0];
                unsigned a2 = ah[r0 * 36 + w1], a3 = ah[(r0 + 8) * 36 + w1];
                unsigned l0 = al[r0 * 36 + w0], l1 = al[(r0 + 8) * 36 + w0];
                unsigned l2 = al[r0 * 36 + w1], l3 = al[(r0 + 8) * 36 + w1];
#pragma unroll
                for (int nt = 0; nt < 4; nt++) {
                    mmabf(acc[mt][nt], a0, a1, a2, a3, bh[nt][0], bh[nt][1]);
                    mmabf(acc[mt][nt], a0, a1, a2, a3, bl[nt][0], bl[nt][1]);
                    mmabf(acc[mt][nt], l0, l1, l2, l3, bh[nt][0], bh[nt][1]);
                }
            }
        }
        __syncthreads();
        if (cc + 2 < 16) issue(cc & 1, cc + 2);
        else cp_commit();
    }
#pragma unroll
    for (int mt = 0; mt < 2; mt++) {
        int r0g = mb * 128 + mw * 32 + mt * 16 + g;
#pragma unroll
        for (int nt = 0; nt < 4; nt++) {
            int c0 = nbk * 64 + nw * 32 + nt * 8 + 2 * tig;
            float2 bv = *(const float2*)&bias[c0];
            *(float2*)&out[(size_t)r0g * VV + c0] =
                make_float2(acc[mt][nt][0] + bv.x, acc[mt][nt][1] + bv.y);
            *(float2*)&out[(size_t)(r0g + 8) * VV + c0] =
                make_float2(acc[mt][nt][2] + bv.x, acc[mt][nt][3] + bv.y);
        }
    }
}

// ---------------- launch ----------------
extern "C" void kernel_launch(void* const* d_in, const int* in_sizes, int n_in,
                              void* d_out, int out_size) {
    (void)in_sizes; (void)n_in; (void)out_size;
    const int* obs = (const int*)d_in[0];
    const float* hidden_init = (const float*)d_in[1];
    const float* kinit = (const float*)d_in[2];
    const float* vinit = (const float*)d_in[3];
    const float* enc_w = (const float*)d_in[4];
    const float* q_w = (const float*)d_in[5];
    const float* q_b = (const float*)d_in[6];
    const float* qn_g = (const float*)d_in[7];
    const float* qn_b = (const float*)d_in[8];
    const float* int_w = (const float*)d_in[9];
    const float* int_b = (const float*)d_in[10];
    const float* intn_g = (const float*)d_in[11];
    const float* intn_b = (const float*)d_in[12];
    const float* fin_w = (const float*)d_in[13];
    const float* fin_b = (const float*)d_in[14];
    const float* fn_g = (const float*)d_in[15];
    const float* fn_b = (const float*)d_in[16];
    const float* dec_w = (const float*)d_in[17];
    const float* dec_b = (const float*)d_in[18];

    float* logits = (float*)d_out;
    float* states_full = logits + (size_t)SS * BB * VV;

    const int DEC_SMEM = 2 * 55296;    // 110592 B (2 stages x 13824 words)
    cudaFuncSetAttribute(k_dec, cudaFuncAttributeMaxDynamicSharedMemorySize, DEC_SMEM);

    unsigned* wd;
    cudaGetSymbolAddress((void**)&wd, g_wd);

    // one-time dec_w conversion (inside the graph; amortized)
    k_cvt_w<<<8192, 256>>>(dec_w, wd, 32000, 1024);
    k_init<<<BB, 256>>>(hidden_init, kinit, vinit, states_full);
    k_embed<<<SS * BB, 256>>>(obs, enc_w);

    for (int s = 0; s < SS; s++) {
        // q = relu(ln([e,hidden] @ q_w.T + q_b)); LN fused into attention kernel
        k_gemm_step<<<dim3(16, KSPLIT), 256>>>(s, 0, q_w, 2048, 2048 / KSPLIT, 1024, 0);
        k_lnq_attn<<<BB, 512>>>(q_b, qn_g, qn_b, s);
        // inter = relu(ln([e,q,attn,hidden] @ int_w.T + int_b)); x order [e,hidden,q,attn]
        k_gemm_step<<<dim3(64, KSPLIT), 256>>>(s, 0, int_w, 4096, 4096 / KSPLIT, 4096, 1);
        k_ln_int<<<BB, 256>>>(int_b, intn_g, intn_b);
        // final = relu(ln(inter @ fin_w.T + fin_b)) -> split k,v,h
        k_gemm_step<<<dim3(48, KSPLIT), 256>>>(-1, 1, fin_w, 4096, 4096 / KSPLIT, 3072, 0);
        k_ln_fin<<<BB, 256>>>(fin_b, fn_g, fn_b, s, states_full);
    }

    // logits = states @ dec_w.T + dec_b
    k_dec<<<dim3(32, VV / 64), 256, DEC_SMEM>>>(dec_b, logits);
}

// round 12
// speedup vs baseline: 1.0078x; 1.0078x over previous
#include <cuda_runtime.h>
#include <math.h>

#define SS 128
#define BB 32
#define VV 32000
#define NINP 1024
#define NHID 1024
#define NHEADS 16
#define HD 64
#define KSPLIT 8

// ---------------- device scratch ----------------
static __device__ float g_emb[(size_t)SS * BB * NINP];       // raw fp32 embeddings
static __device__ float g_xbuf[BB * 3072];                   // [hidden|q|attn] fp32
static __device__ float g_kcache[(size_t)(SS + 1) * BB * NHID];
static __device__ float g_vcache[(size_t)(SS + 1) * BB * NHID];
static __device__ float g_inter[BB * 4096];
static __device__ float g_part[KSPLIT * BB * 4096];          // split-K partials
static __device__ float g_qpe[(size_t)SS * BB * 1024];       // precomputed e @ q_w[:, :1024].T
static __device__ float g_ipe[(size_t)SS * BB * 4096];       // precomputed e @ int_w[:, :1024].T

// ---------------- helpers ----------------
__device__ __forceinline__ unsigned packbf(float e, float o) {
    // word = {lo16 = bf16(e), hi16 = bf16(o)}
    unsigned r;
    asm("cvt.rn.bf16x2.f32 %0, %1, %2;" : "=r"(r) : "f"(o), "f"(e));
    return r;
}
__device__ __forceinline__ void cvtpair(float4 v, unsigned* ph, unsigned* pl) {
    unsigned h0 = packbf(v.x, v.y);
    unsigned h1 = packbf(v.z, v.w);
    float r0 = v.x - __uint_as_float(h0 << 16);
    float r1 = v.y - __uint_as_float(h0 & 0xffff0000u);
    float r2 = v.z - __uint_as_float(h1 << 16);
    float r3 = v.w - __uint_as_float(h1 & 0xffff0000u);
    ph[0] = h0; ph[1] = h1;
    pl[0] = packbf(r0, r1);
    pl[1] = packbf(r2, r3);
}
__device__ __forceinline__ void mmabf(float* c, unsigned a0, unsigned a1, unsigned a2,
                                      unsigned a3, unsigned b0, unsigned b1) {
    asm volatile(
        "mma.sync.aligned.m16n8k16.row.col.f32.bf16.bf16.f32 "
        "{%0,%1,%2,%3},{%4,%5,%6,%7},{%8,%9},{%0,%1,%2,%3};"
        : "+f"(c[0]), "+f"(c[1]), "+f"(c[2]), "+f"(c[3])
        : "r"(a0), "r"(a1), "r"(a2), "r"(a3), "r"(b0), "r"(b1));
}

// ---------------- setup ----------------
__global__ void k_init(const float* __restrict__ h0, const float* __restrict__ kc0,
                       const float* __restrict__ vc0, float* __restrict__ states_full) {
    int b = blockIdx.x, t = threadIdx.x;
    float4 h = ((const float4*)(h0 + b * NHID))[t];
    ((float4*)(g_xbuf + b * 3072))[t] = h;
    ((float4*)(states_full + (size_t)b * NHID))[t] = h;
    ((float4*)(g_kcache + (size_t)b * NHID))[t] = ((const float4*)(kc0 + b * NHID))[t];
    ((float4*)(g_vcache + (size_t)b * NHID))[t] = ((const float4*)(vc0 + b * NHID))[t];
}

__global__ void k_embed(const int* __restrict__ obs, const float* __restrict__ enc_w) {
    int idx = blockIdx.x;  // s*B + b
    int row = obs[idx];
    ((float4*)(g_emb + (size_t)idx * NINP))[threadIdx.x] =
        ((const float4*)(enc_w + (size_t)row * NINP))[threadIdx.x];
}

// ---------------- step GEMM (round-4 mainloop; x is runtime state only) ----------------
// part[b,n] = sum_k x[b,k]*W[n,k]; M=32, N-tile=64, splitK=8.
// xsel 0: x = g_xbuf [hidden|q|attn] (stride 3072); xsel 1: x = g_inter (stride 4096).
// permute (int-GEMM): x col gc<1024 is hidden -> int_w col 3072+gc; else identity.
__global__ __launch_bounds__(256) void k_gemm_step(int xsel, const float* __restrict__ W,
                                                   int K, int klen, int N, int permute) {
    __shared__ unsigned xh[32][36], xl[32][36], wh[64][36], wl[64][36];
    const int tid = threadIdx.x;
    const int nb = blockIdx.x * 64;
    const int k0 = blockIdx.y * klen;
    const int w = tid >> 5, lane = tid & 31, g = lane >> 2, tig = lane & 3;

    const float* xr = xsel ? g_inter : g_xbuf;
    const int xstride = xsel ? 4096 : 3072;

    float acc[2][4] = {};
    float4 xa[2], wa[4];

    auto loadx = [&](int kc) {
#pragma unroll
        for (int i = 0; i < 2; i++) {
            int e = tid + i * 256;
            int r = e >> 4, cg = (e & 15) << 2;
            xa[i] = *(const float4*)(xr + r * xstride + kc + cg);
        }
#pragma unroll
        for (int i = 0; i < 4; i++) {
            int e = tid + i * 256;
            int r = e >> 4, cg = (e & 15) << 2;
            int gc = kc + cg;
            int wc = permute ? ((gc < 1024) ? gc + 3072 : gc) : gc;
            wa[i] = *(const float4*)(W + (size_t)(nb + r) * K + wc);
        }
    };
    auto store = [&]() {
#pragma unroll
        for (int i = 0; i < 2; i++) {
            int e = tid + i * 256;
            int r = e >> 4, wd = (e & 15) * 2;
            cvtpair(xa[i], &xh[r][wd], &xl[r][wd]);
        }
#pragma unroll
        for (int i = 0; i < 4; i++) {
            int e = tid + i * 256;
            int r = e >> 4, wd = (e & 15) * 2;
            cvtpair(wa[i], &wh[r][wd], &wl[r][wd]);
        }
    };

    const int nchunks = klen >> 6;
    loadx(k0);
    for (int c = 0; c < nchunks; c++) {
        store();
        __syncthreads();
        if (c + 1 < nchunks) loadx(k0 + (c + 1) * 64);
#pragma unroll
        for (int s = 0; s < 4; s++) {
            int w0 = s * 8 + tig, w1 = w0 + 4;
            unsigned bh0 = wh[w * 8 + g][w0], bh1 = wh[w * 8 + g][w1];
            unsigned bl0 = wl[w * 8 + g][w0], bl1 = wl[w * 8 + g][w1];
#pragma unroll
            for (int mt = 0; mt < 2; mt++) {
                int r0 = mt * 16 + g;
                unsigned ah0 = xh[r0][w0], ah1 = xh[r0 + 8][w0];
                unsigned ah2 = xh[r0][w1], ah3 = xh[r0 + 8][w1];
                unsigned al0 = xl[r0][w0], al1 = xl[r0 + 8][w0];
                unsigned al2 = xl[r0][w1], al3 = xl[r0 + 8][w1];
                mmabf(acc[mt], ah0, ah1, ah2, ah3, bh0, bh1);
                mmabf(acc[mt], ah0, ah1, ah2, ah3, bl0, bl1);
                mmabf(acc[mt], al0, al1, al2, al3, bh0, bh1);
            }
        }
        __syncthreads();
    }
    float* p = g_part + (size_t)blockIdx.y * 32 * N;
    int n0 = nb + w * 8 + 2 * tig;
#pragma unroll
    for (int mt = 0; mt < 2; mt++) {
        int r0 = mt * 16 + g;
        *(float2*)&p[r0 * N + n0] = make_float2(acc[mt][0], acc[mt][1]);
        *(float2*)&p[(r0 + 8) * N + n0] = make_float2(acc[mt][2], acc[mt][3]);
    }
}

// ---------------- fused LN(q)+relu + attention (round-6 + qpe partial) ----------------
__global__ __launch_bounds__(512) void k_lnq_attn(const float* __restrict__ qb,
                                                  const float* __restrict__ gg,
                                                  const float* __restrict__ bbv, int step) {
    __shared__ float q[1024];
    __shared__ float sc[NHEADS][132];
    __shared__ float r1[16], r2[16];
    int b = blockIdx.x, tid = threadIdx.x, lane = tid & 31, wid = tid >> 5;

    float2 v = *(const float2*)(qb + 2 * tid);
    {
        float2 pe = *(const float2*)(g_qpe + ((size_t)step * BB + b) * 1024 + 2 * tid);
        v.x += pe.x; v.y += pe.y;
    }
#pragma unroll
    for (int j = 0; j < KSPLIT; j++) {
        float2 p = *(const float2*)(g_part + (size_t)j * 32 * 1024 + b * 1024 + 2 * tid);
        v.x += p.x; v.y += p.y;
    }
    float s1 = v.x + v.y, s2 = v.x * v.x + v.y * v.y;
#pragma unroll
    for (int o = 16; o; o >>= 1) {
        s1 += __shfl_xor_sync(0xffffffffu, s1, o);
        s2 += __shfl_xor_sync(0xffffffffu, s2, o);
    }
    if (lane == 0) { r1[wid] = s1; r2[wid] = s2; }
    __syncthreads();
    s1 = 0.f; s2 = 0.f;
#pragma unroll
    for (int i = 0; i < 16; i++) { s1 += r1[i]; s2 += r2[i]; }
    float mu = s1 * (1.f / 1024.f);
    float rstd = rsqrtf(s2 * (1.f / 1024.f) - mu * mu + 1e-5f);
    float q0 = fmaxf((v.x - mu) * rstd * gg[2 * tid] + bbv[2 * tid], 0.f);
    float q1 = fmaxf((v.y - mu) * rstd * gg[2 * tid + 1] + bbv[2 * tid + 1], 0.f);
    q[2 * tid] = q0;
    q[2 * tid + 1] = q1;
    *(float2*)&g_xbuf[b * 3072 + 1024 + 2 * tid] = make_float2(q0, q1);
    __syncthreads();

    const int hh = wid;
    const int L = step + 1;
    const float* qh = q + hh * HD;
    float msc[4], m = -1e30f;
#pragma unroll
    for (int i = 0; i < 4; i++) {
        int c = lane + i * 32;
        float d = -1e30f;
        if (c < L) {
            const float* kr = g_kcache + ((size_t)c * BB + b) * NHID + hh * HD;
            float acc = 0.f;
#pragma unroll
            for (int j = 0; j < 16; j++) {
                float4 kv = *(const float4*)&kr[j * 4];
                acc += qh[j * 4] * kv.x + qh[j * 4 + 1] * kv.y +
                       qh[j * 4 + 2] * kv.z + qh[j * 4 + 3] * kv.w;
            }
            d = acc * 0.125f;
        }
        msc[i] = d;
        m = fmaxf(m, d);
    }
#pragma unroll
    for (int o = 16; o; o >>= 1) m = fmaxf(m, __shfl_xor_sync(0xffffffffu, m, o));
    float se = 0.f;
#pragma unroll
    for (int i = 0; i < 4; i++) {
        float e = expf(msc[i] - m);   // c >= L -> exp(-huge) = 0
        sc[hh][lane + i * 32] = e;
        se += e;
    }
#pragma unroll
    for (int o = 16; o; o >>= 1) se += __shfl_xor_sync(0xffffffffu, se, o);
    float inv = 1.f / se;
    __syncwarp();

    float o0 = 0.f, o1 = 0.f;
    const float* vbase = g_vcache + (size_t)b * NHID + hh * HD + 2 * lane;
#pragma unroll 4
    for (int c = 0; c < L; c++) {
        float wgt = sc[hh][c];
        float2 vv = *(const float2*)(vbase + (size_t)c * BB * NHID);
        o0 += wgt * vv.x;
        o1 += wgt * vv.y;
    }
    *(float2*)&g_xbuf[b * 3072 + 2048 + hh * HD + 2 * lane] = make_float2(o0 * inv, o1 * inv);
}

// ---------------- LN(int)+relu -> g_inter (round-4 + ipe partial) ----------------
__global__ __launch_bounds__(256) void k_ln_int(const float* __restrict__ bias,
                                                const float* __restrict__ gg,
                                                const float* __restrict__ bb2, int step) {
    __shared__ float pre[4096];
    __shared__ float red1[8], red2[8];
    int b = blockIdx.x, tid = threadIdx.x, lane = tid & 31, wid = tid >> 5;
    float s1 = 0.f, s2 = 0.f;
#pragma unroll
    for (int i = 0; i < 4; i++) {
        int c = (tid + i * 256) * 4;
        float4 v = *(const float4*)&bias[c];
        {
            float4 pe = *(const float4*)(g_ipe + ((size_t)step * BB + b) * 4096 + c);
            v.x += pe.x; v.y += pe.y; v.z += pe.z; v.w += pe.w;
        }
#pragma unroll
        for (int j = 0; j < KSPLIT; j++) {
            float4 p = *(const float4*)&g_part[(size_t)j * 32 * 4096 + b * 4096 + c];
            v.x += p.x; v.y += p.y; v.z += p.z; v.w += p.w;
        }
        *(float4*)&pre[c] = v;
        s1 += v.x + v.y + v.z + v.w;
        s2 += v.x * v.x + v.y * v.y + v.z * v.z + v.w * v.w;
    }
#pragma unroll
    for (int o = 16; o; o >>= 1) {
        s1 += __shfl_xor_sync(0xffffffffu, s1, o);
        s2 += __shfl_xor_sync(0xffffffffu, s2, o);
    }
    if (lane == 0) { red1[wid] = s1; red2[wid] = s2; }
    __syncthreads();
    s1 = 0.f; s2 = 0.f;
#pragma unroll
    for (int i = 0; i < 8; i++) { s1 += red1[i]; s2 += red2[i]; }
    float mu = s1 * (1.f / 4096.f);
    float rstd = rsqrtf(s2 * (1.f / 4096.f) - mu * mu + 1e-5f);
#pragma unroll
    for (int i = 0; i < 16; i++) {
        int c = tid + i * 256;
        g_inter[b * 4096 + c] = fmaxf((pre[c] - mu) * rstd * gg[c] + bb2[c], 0.f);
    }
}

// ---------------- LN(fin)+relu -> kcache, vcache, states, hidden (round-4 verbatim) ------
__global__ __launch_bounds__(256) void k_ln_fin(const float* __restrict__ bias,
                                                const float* __restrict__ gg,
                                                const float* __restrict__ bb2, int step,
                                                float* __restrict__ states_full) {
    __shared__ float pre[3072];
    __shared__ float red1[8], red2[8];
    int b = blockIdx.x, tid = threadIdx.x, lane = tid & 31, wid = tid >> 5;
    float s1 = 0.f, s2 = 0.f;
#pragma unroll
    for (int i = 0; i < 3; i++) {
        int c = (tid + i * 256) * 4;
        float4 v = *(const float4*)&bias[c];
#pragma unroll
        for (int j = 0; j < KSPLIT; j++) {
            float4 p = *(const float4*)&g_part[(size_t)j * 32 * 3072 + b * 3072 + c];
            v.x += p.x; v.y += p.y; v.z += p.z; v.w += p.w;
        }
        *(float4*)&pre[c] = v;
        s1 += v.x + v.y + v.z + v.w;
        s2 += v.x * v.x + v.y * v.y + v.z * v.z + v.w * v.w;
    }
#pragma unroll
    for (int o = 16; o; o >>= 1) {
        s1 += __shfl_xor_sync(0xffffffffu, s1, o);
        s2 += __shfl_xor_sync(0xffffffffu, s2, o);
    }
    if (lane == 0) { red1[wid] = s1; red2[wid] = s2; }
    __syncthreads();
    s1 = 0.f; s2 = 0.f;
#pragma unroll
    for (int i = 0; i < 8; i++) { s1 += red1[i]; s2 += red2[i]; }
    float mu = s1 * (1.f / 3072.f);
    float rstd = rsqrtf(s2 * (1.f / 3072.f) - mu * mu + 1e-5f);
#pragma unroll
    for (int i = 0; i < 12; i++) {
        int c = tid + i * 256;
        float y = fmaxf((pre[c] - mu) * rstd * gg[c] + bb2[c], 0.f);
        if (c < 1024) {
            g_kcache[((size_t)(step + 1) * BB + b) * NHID + c] = y;
        } else if (c < 2048) {
            g_vcache[((size_t)(step + 1) * BB + b) * NHID + (c - 1024)] = y;
        } else {
            int d = c - 2048;
            states_full[((size_t)(step + 1) * BB + b) * NHID + d] = y;
            g_xbuf[b * 3072 + d] = y;
        }
    }
}

// ---------------- big GEMM (round-4 k_dec generalized): out = A @ W.T (+ bias) ----------
// A [M][1024] row-major; W [N][ldw] row-major, K = first 1024 cols; out stride ldo.
__global__ __launch_bounds__(256, 1) void k_bigemm(const float* __restrict__ A,
                                                   const float* __restrict__ Wd, int ldw,
                                                   const float* __restrict__ bias,
                                                   float* __restrict__ out, long ldo) {
    __shared__ unsigned ah[128][20], al[128][20], bh_[128][20], bl_[128][20];
    int tid = threadIdx.x;
    int mb = blockIdx.x * 128, nb = blockIdx.y * 128;
    int w = tid >> 5, lane = tid & 31, g = lane >> 2, tig = lane & 3;
    int mw = w >> 2, nw = w & 3;  // 2 m-warps x 4 n-warps
    float acc[4][4][4] = {};
    float4 aa[4], wv[4];

    auto load = [&](int kc) {
#pragma unroll
        for (int i = 0; i < 4; i++) {
            int e = tid + i * 256;
            int r = e >> 3, cg = (e & 7) << 2;
            aa[i] = *(const float4*)(A + (size_t)(mb + r) * 1024 + kc + cg);
            wv[i] = *(const float4*)(Wd + (size_t)(nb + r) * ldw + kc + cg);
        }
    };
    auto store = [&]() {
#pragma unroll
        for (int i = 0; i < 4; i++) {
            int e = tid + i * 256;
            int r = e >> 3, wd = (e & 7) * 2;
            cvtpair(aa[i], &ah[r][wd], &al[r][wd]);
            cvtpair(wv[i], &bh_[r][wd], &bl_[r][wd]);
        }
    };

    load(0);
    for (int c = 0; c < 32; c++) {
        store();
        __syncthreads();
        if (c < 31) load((c + 1) * 32);
#pragma unroll
        for (int s = 0; s < 2; s++) {
            int w0 = s * 8 + tig, w1 = w0 + 4;
            unsigned bh[4][2], bl[4][2];
#pragma unroll
            for (int nt = 0; nt < 4; nt++) {
                int col = nw * 32 + nt * 8 + g;
                bh[nt][0] = bh_[col][w0]; bh[nt][1] = bh_[col][w1];
                bl[nt][0] = bl_[col][w0]; bl[nt][1] = bl_[col][w1];
            }
#pragma unroll
            for (int mt = 0; mt < 4; mt++) {
                int r0 = mw * 64 + mt * 16 + g;
                unsigned a0 = ah[r0][w0], a1 = ah[r0 + 8][w0], a2 = ah[r0][w1], a3 = ah[r0 + 8][w1];
                unsigned l0 = al[r0][w0], l1 = al[r0 + 8][w0], l2 = al[r0][w1], l3 = al[r0 + 8][w1];
#pragma unroll
                for (int nt = 0; nt < 4; nt++) {
                    mmabf(acc[mt][nt], a0, a1, a2, a3, bh[nt][0], bh[nt][1]);
                    mmabf(acc[mt][nt], a0, a1, a2, a3, bl[nt][0], bl[nt][1]);
                    mmabf(acc[mt][nt], l0, l1, l2, l3, bh[nt][0], bh[nt][1]);
                }
            }
        }
        __syncthreads();
    }
#pragma unroll
    for (int mt = 0; mt < 4; mt++) {
        int r0 = mb + mw * 64 + mt * 16 + g;
#pragma unroll
        for (int nt = 0; nt < 4; nt++) {
            int c0 = nb + nw * 32 + nt * 8 + 2 * tig;
            float2 bv = bias ? *(const float2*)&bias[c0] : make_float2(0.f, 0.f);
            *(float2*)&out[(size_t)r0 * ldo + c0] =
                make_float2(acc[mt][nt][0] + bv.x, acc[mt][nt][1] + bv.y);
            *(float2*)&out[(size_t)(r0 + 8) * ldo + c0] =
                make_float2(acc[mt][nt][2] + bv.x, acc[mt][nt][3] + bv.y);
        }
    }
}

// ---------------- launch ----------------
extern "C" void kernel_launch(void* const* d_in, const int* in_sizes, int n_in,
                              void* d_out, int out_size) {
    (void)in_sizes; (void)n_in; (void)out_size;
    const int* obs = (const int*)d_in[0];
    const float* hidden_init = (const float*)d_in[1];
    const float* kinit = (const float*)d_in[2];
    const float* vinit = (const float*)d_in[3];
    const float* enc_w = (const float*)d_in[4];
    const float* q_w = (const float*)d_in[5];
    const float* q_b = (const float*)d_in[6];
    const float* qn_g = (const float*)d_in[7];
    const float* qn_b = (const float*)d_in[8];
    const float* int_w = (const float*)d_in[9];
    const float* int_b = (const float*)d_in[10];
    const float* intn_g = (const float*)d_in[11];
    const float* intn_b = (const float*)d_in[12];
    const float* fin_w = (const float*)d_in[13];
    const float* fin_b = (const float*)d_in[14];
    const float* fn_g = (const float*)d_in[15];
    const float* fn_b = (const float*)d_in[16];
    const float* dec_w = (const float*)d_in[17];
    const float* dec_b = (const float*)d_in[18];

    float* logits = (float*)d_out;
    float* states_full = logits + (size_t)SS * BB * VV;

    float *qpe, *ipe;
    cudaGetSymbolAddress((void**)&qpe, g_qpe);
    cudaGetSymbolAddress((void**)&ipe, g_ipe);
    float* embp;
    cudaGetSymbolAddress((void**)&embp, g_emb);

    k_init<<<BB, 256>>>(hidden_init, kinit, vinit, states_full);
    k_embed<<<SS * BB, 256>>>(obs, enc_w);

    // one-time: embedding contributions for all steps
    // qpe[s*B+b][n] = e(s,b) . q_w[n][0:1024]      (q_w row stride 2048)
    k_bigemm<<<dim3(32, 8), 256>>>(embp, q_w, 2048, nullptr, qpe, 1024);
    // ipe[s*B+b][n] = e(s,b) . int_w[n][0:1024]    (int_w row stride 4096)
    k_bigemm<<<dim3(32, 32), 256>>>(embp, int_w, 4096, nullptr, ipe, 4096);

    for (int s = 0; s < SS; s++) {
        // q partial (hidden half only; e-half precomputed): K cols 1024..2047 of q_w
        k_gemm_step<<<dim3(16, KSPLIT), 256>>>(0, q_w + 1024, 2048, 1024 / KSPLIT, 1024, 0);
        k_lnq_attn<<<BB, 512>>>(q_b, qn_g, qn_b, s);
        // int partial over x=[hidden|q|attn] (e-quarter precomputed)
        k_gemm_step<<<dim3(64, KSPLIT), 256>>>(0, int_w, 4096, 3072 / KSPLIT, 4096, 1);
        k_ln_int<<<BB, 256>>>(int_b, intn_g, intn_b, s);
        // final = relu(ln(inter @ fin_w.T + fin_b)) -> split k,v,h
        k_gemm_step<<<dim3(48, KSPLIT), 256>>>(1, fin_w, 4096, 4096 / KSPLIT, 3072, 0);
        k_ln_fin<<<BB, 256>>>(fin_b, fn_g, fn_b, s, states_full);
    }

    // logits = states @ dec_w.T + dec_b  (states = states_full rows 1..S)
    k_bigemm<<<dim3(32, VV / 128), 256>>>(states_full + BB * NHID, dec_w, 1024, dec_b,
                                          logits, VV);
}

// round 13
// speedup vs baseline: 1.0111x; 1.0033x over previous
#include <cuda_runtime.h>
#include <math.h>

#define SS 128
#define BB 32
#define VV 32000
#define NINP 1024
#define NHID 1024
#define NHEADS 16
#define HD 64
#define KSPLIT 8
#define CHSTEP 8   // decoder chunk = 8 steps = 256 rows

// ---------------- device scratch ----------------
static __device__ float g_emb[(size_t)SS * BB * NINP];       // raw fp32 embeddings
static __device__ float g_xbuf[BB * 3072];                   // [hidden|q|attn] fp32
static __device__ float g_kcache[(size_t)(SS + 1) * BB * NHID];
static __device__ float g_vcache[(size_t)(SS + 1) * BB * NHID];
static __device__ float g_inter[BB * 4096];
static __device__ float g_part[KSPLIT * BB * 4096];          // split-K partials
static __device__ float g_qpe[(size_t)SS * BB * 1024];       // e @ q_w[:, :1024].T
static __device__ float g_ipe[(size_t)SS * BB * 4096];       // e @ int_w[:, :1024].T
// decoder blobs (bf16 hi/lo smem images). W chunk = 4608 words = 1152 uint4;
// A chunk = 9216 words = 2304 uint4.
static __device__ uint4 g_wd[(size_t)500 * 16 * 1152];       // dec_w [32000][1024]
static __device__ uint4 g_aimg[(size_t)32 * 16 * 2304];      // states rows (32 mb x 16 gc)

// ---------------- helpers ----------------
__device__ __forceinline__ unsigned packbf(float e, float o) {
    unsigned r;
    asm("cvt.rn.bf16x2.f32 %0, %1, %2;" : "=r"(r) : "f"(o), "f"(e));
    return r;
}
__device__ __forceinline__ void splitpair(float v0, float v1, unsigned& h, unsigned& l) {
    h = packbf(v0, v1);
    float r0 = v0 - __uint_as_float(h << 16);
    float r1 = v1 - __uint_as_float(h & 0xffff0000u);
    l = packbf(r0, r1);
}
__device__ __forceinline__ void cvtpair(float4 v, unsigned* ph, unsigned* pl) {
    unsigned h0 = packbf(v.x, v.y);
    unsigned h1 = packbf(v.z, v.w);
    float r0 = v.x - __uint_as_float(h0 << 16);
    float r1 = v.y - __uint_as_float(h0 & 0xffff0000u);
    float r2 = v.z - __uint_as_float(h1 << 16);
    float r3 = v.w - __uint_as_float(h1 & 0xffff0000u);
    ph[0] = h0; ph[1] = h1;
    pl[0] = packbf(r0, r1);
    pl[1] = packbf(r2, r3);
}
__device__ __forceinline__ void mmabf(float* c, unsigned a0, unsigned a1, unsigned a2,
                                      unsigned a3, unsigned b0, unsigned b1) {
    asm volatile(
        "mma.sync.aligned.m16n8k16.row.col.f32.bf16.bf16.f32 "
        "{%0,%1,%2,%3},{%4,%5,%6,%7},{%8,%9},{%0,%1,%2,%3};"
        : "+f"(c[0]), "+f"(c[1]), "+f"(c[2]), "+f"(c[3])
        : "r"(a0), "r"(a1), "r"(a2), "r"(a3), "r"(b0), "r"(b1));
}
__device__ __forceinline__ void cp_commit() { asm volatile("cp.async.commit_group;"); }
template <int N>
__device__ __forceinline__ void cp_wait() { asm volatile("cp.async.wait_group %0;" ::"n"(N)); }
#define CPA16(d, s) asm volatile("cp.async.cg.shared.global [%0], [%1], 16;" ::"r"(d), "l"(s))

// ---------------- one-time dec_w conversion into blob layout ----------------
__global__ void k_cvt_w(const float* __restrict__ src, unsigned* __restrict__ dst,
                        int N, int K) {
    long total = (long)N * (K >> 1);
    long stride = (long)gridDim.x * blockDim.x;
    int KC = K >> 6;
    for (long i = (long)blockIdx.x * blockDim.x + threadIdx.x; i < total; i += stride) {
        int n = (int)(i / (K >> 1));
        int kw = (int)(i - (long)n * (K >> 1));
        float2 v = *(const float2*)(src + (size_t)n * K + 2 * kw);
        unsigned h, l;
        splitpair(v.x, v.y, h, l);
        int nt = n >> 6, r = n & 63, gc = kw >> 5, w = kw & 31;
        size_t base = ((size_t)nt * KC + gc) * 4608;   // words
        dst[base + r * 36 + w] = h;
        dst[base + 2304 + r * 36 + w] = l;
    }
}

// ---------------- setup ----------------
__global__ void k_init(const float* __restrict__ h0, const float* __restrict__ kc0,
                       const float* __restrict__ vc0, float* __restrict__ states_full) {
    int b = blockIdx.x, t = threadIdx.x;
    float4 h = ((const float4*)(h0 + b * NHID))[t];
    ((float4*)(g_xbuf + b * 3072))[t] = h;
    ((float4*)(states_full + (size_t)b * NHID))[t] = h;
    ((float4*)(g_kcache + (size_t)b * NHID))[t] = ((const float4*)(kc0 + b * NHID))[t];
    ((float4*)(g_vcache + (size_t)b * NHID))[t] = ((const float4*)(vc0 + b * NHID))[t];
}

__global__ void k_embed(const int* __restrict__ obs, const float* __restrict__ enc_w) {
    int idx = blockIdx.x;  // s*B + b
    int row = obs[idx];
    ((float4*)(g_emb + (size_t)idx * NINP))[threadIdx.x] =
        ((const float4*)(enc_w + (size_t)row * NINP))[threadIdx.x];
}

// ---------------- step GEMM (round-4 mainloop; x is runtime state only) ----------------
__global__ __launch_bounds__(256) void k_gemm_step(int xsel, const float* __restrict__ W,
                                                   int K, int klen, int N, int permute) {
    __shared__ unsigned xh[32][36], xl[32][36], wh[64][36], wl[64][36];
    const int tid = threadIdx.x;
    const int nb = blockIdx.x * 64;
    const int k0 = blockIdx.y * klen;
    const int w = tid >> 5, lane = tid & 31, g = lane >> 2, tig = lane & 3;

    const float* xr = xsel ? g_inter : g_xbuf;
    const int xstride = xsel ? 4096 : 3072;

    float acc[2][4] = {};
    float4 xa[2], wa[4];

    auto loadx = [&](int kc) {
#pragma unroll
        for (int i = 0; i < 2; i++) {
            int e = tid + i * 256;
            int r = e >> 4, cg = (e & 15) << 2;
            xa[i] = *(const float4*)(xr + r * xstride + kc + cg);
        }
#pragma unroll
        for (int i = 0; i < 4; i++) {
            int e = tid + i * 256;
            int r = e >> 4, cg = (e & 15) << 2;
            int gc = kc + cg;
            int wc = permute ? ((gc < 1024) ? gc + 3072 : gc) : gc;
            wa[i] = *(const float4*)(W + (size_t)(nb + r) * K + wc);
        }
    };
    auto store = [&]() {
#pragma unroll
        for (int i = 0; i < 2; i++) {
            int e = tid + i * 256;
            int r = e >> 4, wd = (e & 15) * 2;
            cvtpair(xa[i], &xh[r][wd], &xl[r][wd]);
        }
#pragma unroll
        for (int i = 0; i < 4; i++) {
            int e = tid + i * 256;
            int r = e >> 4, wd = (e & 15) * 2;
            cvtpair(wa[i], &wh[r][wd], &wl[r][wd]);
        }
    };

    const int nchunks = klen >> 6;
    loadx(k0);
    for (int c = 0; c < nchunks; c++) {
        store();
        __syncthreads();
        if (c + 1 < nchunks) loadx(k0 + (c + 1) * 64);
#pragma unroll
        for (int s = 0; s < 4; s++) {
            int w0 = s * 8 + tig, w1 = w0 + 4;
            unsigned bh0 = wh[w * 8 + g][w0], bh1 = wh[w * 8 + g][w1];
            unsigned bl0 = wl[w * 8 + g][w0], bl1 = wl[w * 8 + g][w1];
#pragma unroll
            for (int mt = 0; mt < 2; mt++) {
                int r0 = mt * 16 + g;
                unsigned ah0 = xh[r0][w0], ah1 = xh[r0 + 8][w0];
                unsigned ah2 = xh[r0][w1], ah3 = xh[r0 + 8][w1];
                unsigned al0 = xl[r0][w0], al1 = xl[r0 + 8][w0];
                unsigned al2 = xl[r0][w1], al3 = xl[r0 + 8][w1];
                mmabf(acc[mt], ah0, ah1, ah2, ah3, bh0, bh1);
                mmabf(acc[mt], ah0, ah1, ah2, ah3, bl0, bl1);
                mmabf(acc[mt], al0, al1, al2, al3, bh0, bh1);
            }
        }
        __syncthreads();
    }
    float* p = g_part + (size_t)blockIdx.y * 32 * N;
    int n0 = nb + w * 8 + 2 * tig;
#pragma unroll
    for (int mt = 0; mt < 2; mt++) {
        int r0 = mt * 16 + g;
        *(float2*)&p[r0 * N + n0] = make_float2(acc[mt][0], acc[mt][1]);
        *(float2*)&p[(r0 + 8) * N + n0] = make_float2(acc[mt][2], acc[mt][3]);
    }
}

// ---------------- fused LN(q)+relu + attention (round-6 + qpe partial) ----------------
__global__ __launch_bounds__(512) void k_lnq_attn(const float* __restrict__ qb,
                                                  const float* __restrict__ gg,
                                                  const float* __restrict__ bbv, int step) {
    __shared__ float q[1024];
    __shared__ float sc[NHEADS][132];
    __shared__ float r1[16], r2[16];
    int b = blockIdx.x, tid = threadIdx.x, lane = tid & 31, wid = tid >> 5;

    float2 v = *(const float2*)(qb + 2 * tid);
    {
        float2 pe = *(const float2*)(g_qpe + ((size_t)step * BB + b) * 1024 + 2 * tid);
        v.x += pe.x; v.y += pe.y;
    }
#pragma unroll
    for (int j = 0; j < KSPLIT; j++) {
        float2 p = *(const float2*)(g_part + (size_t)j * 32 * 1024 + b * 1024 + 2 * tid);
        v.x += p.x; v.y += p.y;
    }
    float s1 = v.x + v.y, s2 = v.x * v.x + v.y * v.y;
#pragma unroll
    for (int o = 16; o; o >>= 1) {
        s1 += __shfl_xor_sync(0xffffffffu, s1, o);
        s2 += __shfl_xor_sync(0xffffffffu, s2, o);
    }
    if (lane == 0) { r1[wid] = s1; r2[wid] = s2; }
    __syncthreads();
    s1 = 0.f; s2 = 0.f;
#pragma unroll
    for (int i = 0; i < 16; i++) { s1 += r1[i]; s2 += r2[i]; }
    float mu = s1 * (1.f / 1024.f);
    float rstd = rsqrtf(s2 * (1.f / 1024.f) - mu * mu + 1e-5f);
    float q0 = fmaxf((v.x - mu) * rstd * gg[2 * tid] + bbv[2 * tid], 0.f);
    float q1 = fmaxf((v.y - mu) * rstd * gg[2 * tid + 1] + bbv[2 * tid + 1], 0.f);
    q[2 * tid] = q0;
    q[2 * tid + 1] = q1;
    *(float2*)&g_xbuf[b * 3072 + 1024 + 2 * tid] = make_float2(q0, q1);
    __syncthreads();

    const int hh = wid;
    const int L = step + 1;
    const float* qh = q + hh * HD;
    float msc[4], m = -1e30f;
#pragma unroll
    for (int i = 0; i < 4; i++) {
        int c = lane + i * 32;
        float d = -1e30f;
        if (c < L) {
            const float* kr = g_kcache + ((size_t)c * BB + b) * NHID + hh * HD;
            float acc = 0.f;
#pragma unroll
            for (int j = 0; j < 16; j++) {
                float4 kv = *(const float4*)&kr[j * 4];
                acc += qh[j * 4] * kv.x + qh[j * 4 + 1] * kv.y +
                       qh[j * 4 + 2] * kv.z + qh[j * 4 + 3] * kv.w;
            }
            d = acc * 0.125f;
        }
        msc[i] = d;
        m = fmaxf(m, d);
    }
#pragma unroll
    for (int o = 16; o; o >>= 1) m = fmaxf(m, __shfl_xor_sync(0xffffffffu, m, o));
    float se = 0.f;
#pragma unroll
    for (int i = 0; i < 4; i++) {
        float e = expf(msc[i] - m);   // c >= L -> exp(-huge) = 0
        sc[hh][lane + i * 32] = e;
        se += e;
    }
#pragma unroll
    for (int o = 16; o; o >>= 1) se += __shfl_xor_sync(0xffffffffu, se, o);
    float inv = 1.f / se;
    __syncwarp();

    float o0 = 0.f, o1 = 0.f;
    const float* vbase = g_vcache + (size_t)b * NHID + hh * HD + 2 * lane;
#pragma unroll 4
    for (int c = 0; c < L; c++) {
        float wgt = sc[hh][c];
        float2 vv = *(const float2*)(vbase + (size_t)c * BB * NHID);
        o0 += wgt * vv.x;
        o1 += wgt * vv.y;
    }
    *(float2*)&g_xbuf[b * 3072 + 2048 + hh * HD + 2 * lane] = make_float2(o0 * inv, o1 * inv);
}

// ---------------- LN(int)+relu -> g_inter (round-4 + ipe partial) ----------------
__global__ __launch_bounds__(256) void k_ln_int(const float* __restrict__ bias,
                                                const float* __restrict__ gg,
                                                const float* __restrict__ bb2, int step) {
    __shared__ float pre[4096];
    __shared__ float red1[8], red2[8];
    int b = blockIdx.x, tid = threadIdx.x, lane = tid & 31, wid = tid >> 5;
    float s1 = 0.f, s2 = 0.f;
#pragma unroll
    for (int i = 0; i < 4; i++) {
        int c = (tid + i * 256) * 4;
        float4 v = *(const float4*)&bias[c];
        {
            float4 pe = *(const float4*)(g_ipe + ((size_t)step * BB + b) * 4096 + c);
            v.x += pe.x; v.y += pe.y; v.z += pe.z; v.w += pe.w;
        }
#pragma unroll
        for (int j = 0; j < KSPLIT; j++) {
            float4 p = *(const float4*)&g_part[(size_t)j * 32 * 4096 + b * 4096 + c];
            v.x += p.x; v.y += p.y; v.z += p.z; v.w += p.w;
        }
        *(float4*)&pre[c] = v;
        s1 += v.x + v.y + v.z + v.w;
        s2 += v.x * v.x + v.y * v.y + v.z * v.z + v.w * v.w;
    }
#pragma unroll
    for (int o = 16; o; o >>= 1) {
        s1 += __shfl_xor_sync(0xffffffffu, s1, o);
        s2 += __shfl_xor_sync(0xffffffffu, s2, o);
    }
    if (lane == 0) { red1[wid] = s1; red2[wid] = s2; }
    __syncthreads();
    s1 = 0.f; s2 = 0.f;
#pragma unroll
    for (int i = 0; i < 8; i++) { s1 += red1[i]; s2 += red2[i]; }
    float mu = s1 * (1.f / 4096.f);
    float rstd = rsqrtf(s2 * (1.f / 4096.f) - mu * mu + 1e-5f);
#pragma unroll
    for (int i = 0; i < 16; i++) {
        int c = tid + i * 256;
        g_inter[b * 4096 + c] = fmaxf((pre[c] - mu) * rstd * gg[c] + bb2[c], 0.f);
    }
}

// ---------------- LN(fin)+relu -> caches/states/hidden + decoder-A blob ----------------
__global__ __launch_bounds__(256) void k_ln_fin(const float* __restrict__ bias,
                                                const float* __restrict__ gg,
                                                const float* __restrict__ bb2, int step,
                                                float* __restrict__ states_full) {
    __shared__ float pre[3072];
    __shared__ float red1[8], red2[8];
    int b = blockIdx.x, tid = threadIdx.x, lane = tid & 31, wid = tid >> 5;
    float s1 = 0.f, s2 = 0.f;
#pragma unroll
    for (int i = 0; i < 3; i++) {
        int c = (tid + i * 256) * 4;
        float4 v = *(const float4*)&bias[c];
#pragma unroll
        for (int j = 0; j < KSPLIT; j++) {
            float4 p = *(const float4*)&g_part[(size_t)j * 32 * 3072 + b * 3072 + c];
            v.x += p.x; v.y += p.y; v.z += p.z; v.w += p.w;
        }
        *(float4*)&pre[c] = v;
        s1 += v.x + v.y + v.z + v.w;
        s2 += v.x * v.x + v.y * v.y + v.z * v.z + v.w * v.w;
    }
#pragma unroll
    for (int o = 16; o; o >>= 1) {
        s1 += __shfl_xor_sync(0xffffffffu, s1, o);
        s2 += __shfl_xor_sync(0xffffffffu, s2, o);
    }
    if (lane == 0) { red1[wid] = s1; red2[wid] = s2; }
    __syncthreads();
    s1 = 0.f; s2 = 0.f;
#pragma unroll
    for (int i = 0; i < 8; i++) { s1 += red1[i]; s2 += red2[i]; }
    float mu = s1 * (1.f / 3072.f);
    float rstd = rsqrtf(s2 * (1.f / 3072.f) - mu * mu + 1e-5f);
#pragma unroll
    for (int i = 0; i < 6; i++) {
        int c2 = 2 * (tid + i * 256);
        float y0 = fmaxf((pre[c2] - mu) * rstd * gg[c2] + bb2[c2], 0.f);
        float y1 = fmaxf((pre[c2 + 1] - mu) * rstd * gg[c2 + 1] + bb2[c2 + 1], 0.f);
        if (c2 < 1024) {
            *(float2*)&g_kcache[((size_t)(step + 1) * BB + b) * NHID + c2] = make_float2(y0, y1);
        } else if (c2 < 2048) {
            *(float2*)&g_vcache[((size_t)(step + 1) * BB + b) * NHID + (c2 - 1024)] =
                make_float2(y0, y1);
        } else {
            int d = c2 - 2048;
            *(float2*)&states_full[((size_t)(step + 1) * BB + b) * NHID + d] = make_float2(y0, y1);
            *(float2*)&g_xbuf[b * 3072 + d] = make_float2(y0, y1);
            unsigned h_, l_;
            splitpair(y0, y1, h_, l_);
            int ar = step * 32 + b;
            unsigned* a = (unsigned*)g_aimg + ((size_t)((ar >> 7) * 16 + (d >> 6))) * 9216 +
                          (ar & 127) * 36 + ((d & 63) >> 1);
            a[0] = h_;
            a[4608] = l_;
        }
    }
}

// ---------------- decoder chunk: 128m x 64n tiles, cp.async blobs (round-11 + mb0) -------
__global__ __launch_bounds__(256, 2) void k_dec(int mb0, const float* __restrict__ bias,
                                                float* __restrict__ out) {
    extern __shared__ uint4 dsm[];
    unsigned sb = (unsigned)__cvta_generic_to_shared(dsm);
    const int tid = threadIdx.x;
    const int mb = mb0 + blockIdx.x, nbk = blockIdx.y;
    const int w = tid >> 5, lane = tid & 31, g = lane >> 2, tig = lane & 3;
    const int mw = w >> 1, nw = w & 1;
    float acc[2][4][4] = {};

    auto issue = [&](int stage, int gc) {
        const uint4* asrc = g_aimg + ((size_t)(mb * 16 + gc)) * 2304;
        const uint4* wsrc = g_wd + ((size_t)(nbk * 16 + gc)) * 1152;
        unsigned db = sb + stage * 55296;
        for (int u = tid; u < 3456; u += 256) {
            const uint4* s_ = (u < 2304) ? (asrc + u) : (wsrc + (u - 2304));
            CPA16(db + u * 16, s_);
        }
        cp_commit();
    };

    issue(0, 0);
    issue(1, 1);
    for (int cc = 0; cc < 16; cc++) {
        cp_wait<1>();
        __syncthreads();
        const unsigned* st = (const unsigned*)dsm + (cc & 1) * 13824;
        const unsigned* ah = st;
        const unsigned* al = st + 4608;
        const unsigned* wh = st + 9216;
        const unsigned* wl = st + 11520;
#pragma unroll
        for (int s = 0; s < 4; s++) {
            int w0 = s * 8 + tig, w1 = w0 + 4;
            unsigned bh[4][2], bl[4][2];
#pragma unroll
            for (int nt = 0; nt < 4; nt++) {
                int col = nw * 32 + nt * 8 + g;
                bh[nt][0] = wh[col * 36 + w0];
                bh[nt][1] = wh[col * 36 + w1];
                bl[nt][0] = wl[col * 36 + w0];
                bl[nt][1] = wl[col * 36 + w1];
            }
#pragma unroll
            for (int mt = 0; mt < 2; mt++) {
                int r0 = mw * 32 + mt * 16 + g;
                unsigned a0 = ah[r0 * 36 + w0], a1 = ah[(r0 + 8) * 36 + w0];
                unsigned a2 = ah[r0 * 36 + w1], a3 = ah[(r0 + 8) * 36 + w1];
                unsigned l0 = al[r0 * 36 + w0], l1 = al[(r0 + 8) * 36 + w0];
                unsigned l2 = al[r0 * 36 + w1], l3 = al[(r0 + 8) * 36 + w1];
#pragma unroll
                for (int nt = 0; nt < 4; nt++) {
                    mmabf(acc[mt][nt], a0, a1, a2, a3, bh[nt][0], bh[nt][1]);
                    mmabf(acc[mt][nt], a0, a1, a2, a3, bl[nt][0], bl[nt][1]);
                    mmabf(acc[mt][nt], l0, l1, l2, l3, bh[nt][0], bh[nt][1]);
                }
            }
        }
        __syncthreads();
        if (cc + 2 < 16) issue(cc & 1, cc + 2);
        else cp_commit();
    }
#pragma unroll
    for (int mt = 0; mt < 2; mt++) {
        int r0g = mb * 128 + mw * 32 + mt * 16 + g;
#pragma unroll
        for (int nt = 0; nt < 4; nt++) {
            int c0 = nbk * 64 + nw * 32 + nt * 8 + 2 * tig;
            float2 bv = *(const float2*)&bias[c0];
            *(float2*)&out[(size_t)r0g * VV + c0] =
                make_float2(acc[mt][nt][0] + bv.x, acc[mt][nt][1] + bv.y);
            *(float2*)&out[(size_t)(r0g + 8) * VV + c0] =
                make_float2(acc[mt][nt][2] + bv.x, acc[mt][nt][3] + bv.y);
        }
    }
}

// ---------------- big GEMM for precomputes: out = A @ W.T ----------------
__global__ __launch_bounds__(256, 1) void k_bigemm(const float* __restrict__ A,
                                                   const float* __restrict__ Wd, int ldw,
                                                   float* __restrict__ out, long ldo) {
    __shared__ unsigned ah[128][20], al[128][20], bh_[128][20], bl_[128][20];
    int tid = threadIdx.x;
    int mb = blockIdx.x * 128, nb = blockIdx.y * 128;
    int w = tid >> 5, lane = tid & 31, g = lane >> 2, tig = lane & 3;
    int mw = w >> 2, nw = w & 3;
    float acc[4][4][4] = {};
    float4 aa[4], wv[4];

    auto load = [&](int kc) {
#pragma unroll
        for (int i = 0; i < 4; i++) {
            int e = tid + i * 256;
            int r = e >> 3, cg = (e & 7) << 2;
            aa[i] = *(const float4*)(A + (size_t)(mb + r) * 1024 + kc + cg);
            wv[i] = *(const float4*)(Wd + (size_t)(nb + r) * ldw + kc + cg);
        }
    };
    auto store = [&]() {
#pragma unroll
        for (int i = 0; i < 4; i++) {
            int e = tid + i * 256;
            int r = e >> 3, wd = (e & 7) * 2;
            cvtpair(aa[i], &ah[r][wd], &al[r][wd]);
            cvtpair(wv[i], &bh_[r][wd], &bl_[r][wd]);
        }
    };

    load(0);
    for (int c = 0; c < 32; c++) {
        store();
        __syncthreads();
        if (c < 31) load((c + 1) * 32);
#pragma unroll
        for (int s = 0; s < 2; s++) {
            int w0 = s * 8 + tig, w1 = w0 + 4;
            unsigned bh[4][2], bl[4][2];
#pragma unroll
            for (int nt = 0; nt < 4; nt++) {
                int col = nw * 32 + nt * 8 + g;
                bh[nt][0] = bh_[col][w0]; bh[nt][1] = bh_[col][w1];
                bl[nt][0] = bl_[col][w0]; bl[nt][1] = bl_[col][w1];
            }
#pragma unroll
            for (int mt = 0; mt < 4; mt++) {
                int r0 = mw * 64 + mt * 16 + g;
                unsigned a0 = ah[r0][w0], a1 = ah[r0 + 8][w0], a2 = ah[r0][w1], a3 = ah[r0 + 8][w1];
                unsigned l0 = al[r0][w0], l1 = al[r0 + 8][w0], l2 = al[r0][w1], l3 = al[r0 + 8][w1];
#pragma unroll
                for (int nt = 0; nt < 4; nt++) {
                    mmabf(acc[mt][nt], a0, a1, a2, a3, bh[nt][0], bh[nt][1]);
                    mmabf(acc[mt][nt], a0, a1, a2, a3, bl[nt][0], bl[nt][1]);
                    mmabf(acc[mt][nt], l0, l1, l2, l3, bh[nt][0], bh[nt][1]);
                }
            }
        }
        __syncthreads();
    }
#pragma unroll
    for (int mt = 0; mt < 4; mt++) {
        int r0 = mb + mw * 64 + mt * 16 + g;
#pragma unroll
        for (int nt = 0; nt < 4; nt++) {
            int c0 = nb + nw * 32 + nt * 8 + 2 * tig;
            *(float2*)&out[(size_t)r0 * ldo + c0] = make_float2(acc[mt][nt][0], acc[mt][nt][1]);
            *(float2*)&out[(size_t)(r0 + 8) * ldo + c0] = make_float2(acc[mt][nt][2], acc[mt][nt][3]);
        }
    }
}

// ---------------- launch ----------------
static cudaStream_t g_s2 = nullptr;
static cudaEvent_t g_evFork, g_evPre, g_evDec, g_evStep[SS / CHSTEP];

extern "C" void kernel_launch(void* const* d_in, const int* in_sizes, int n_in,
                              void* d_out, int out_size) {
    (void)in_sizes; (void)n_in; (void)out_size;
    const int* obs = (const int*)d_in[0];
    const float* hidden_init = (const float*)d_in[1];
    const float* kinit = (const float*)d_in[2];
    const float* vinit = (const float*)d_in[3];
    const float* enc_w = (const float*)d_in[4];
    const float* q_w = (const float*)d_in[5];
    const float* q_b = (const float*)d_in[6];
    const float* qn_g = (const float*)d_in[7];
    const float* qn_b = (const float*)d_in[8];
    const float* int_w = (const float*)d_in[9];
    const float* int_b = (const float*)d_in[10];
    const float* intn_g = (const float*)d_in[11];
    const float* intn_b = (const float*)d_in[12];
    const float* fin_w = (const float*)d_in[13];
    const float* fin_b = (const float*)d_in[14];
    const float* fn_g = (const float*)d_in[15];
    const float* fn_b = (const float*)d_in[16];
    const float* dec_w = (const float*)d_in[17];
    const float* dec_b = (const float*)d_in[18];

    float* logits = (float*)d_out;
    float* states_full = logits + (size_t)SS * BB * VV;

    if (!g_s2) {
        cudaStreamCreateWithFlags(&g_s2, cudaStreamNonBlocking);
        cudaEventCreateWithFlags(&g_evFork, cudaEventDisableTiming);
        cudaEventCreateWithFlags(&g_evPre, cudaEventDisableTiming);
        cudaEventCreateWithFlags(&g_evDec, cudaEventDisableTiming);
        for (int i = 0; i < SS / CHSTEP; i++)
            cudaEventCreateWithFlags(&g_evStep[i], cudaEventDisableTiming);
    }

    const int DEC_SMEM = 2 * 55296;    // 110592 B (2 stages x 13824 words)
    cudaFuncSetAttribute(k_dec, cudaFuncAttributeMaxDynamicSharedMemorySize, DEC_SMEM);

    unsigned* wd;
    cudaGetSymbolAddress((void**)&wd, g_wd);
    float *qpe, *ipe, *embp;
    cudaGetSymbolAddress((void**)&qpe, g_qpe);
    cudaGetSymbolAddress((void**)&ipe, g_ipe);
    cudaGetSymbolAddress((void**)&embp, g_emb);

    k_init<<<BB, 256>>>(hidden_init, kinit, vinit, states_full);
    k_embed<<<SS * BB, 256>>>(obs, enc_w);

    // fork side stream: dec_w blob conversion + qpe precompute
    cudaEventRecord(g_evFork, 0);
    cudaStreamWaitEvent(g_s2, g_evFork, 0);
    k_cvt_w<<<8192, 256, 0, g_s2>>>(dec_w, wd, 32000, 1024);
    k_bigemm<<<dim3(32, 8), 256, 0, g_s2>>>(embp, q_w, 2048, qpe, 1024);
    cudaEventRecord(g_evPre, g_s2);
    // main stream: ipe precompute (larger) runs concurrently
    k_bigemm<<<dim3(32, 32), 256>>>(embp, int_w, 4096, ipe, 4096);
    cudaStreamWaitEvent(0, g_evPre, 0);   // qpe needed by attn of step 0

    for (int s = 0; s < SS; s++) {
        // q partial (hidden half; e-half precomputed): K cols 1024..2047 of q_w
        k_gemm_step<<<dim3(16, KSPLIT), 256>>>(0, q_w + 1024, 2048, 1024 / KSPLIT, 1024, 0);
        k_lnq_attn<<<BB, 512>>>(q_b, qn_g, qn_b, s);
        // int partial over x=[hidden|q|attn] (e-quarter precomputed)
        k_gemm_step<<<dim3(64, KSPLIT), 256>>>(0, int_w, 4096, 3072 / KSPLIT, 4096, 1);
        k_ln_int<<<BB, 256>>>(int_b, intn_g, intn_b, s);
        // final = relu(ln(inter @ fin_w.T + fin_b)) -> split k,v,h (+ decoder-A blob)
        k_gemm_step<<<dim3(48, KSPLIT), 256>>>(1, fin_w, 4096, 4096 / KSPLIT, 3072, 0);
        k_ln_fin<<<BB, 256>>>(fin_b, fn_g, fn_b, s, states_full);

        // every CHSTEP steps, decode the finished rows on the side stream
        if ((s & (CHSTEP - 1)) == (CHSTEP - 1)) {
            int c = s / CHSTEP;
            cudaEventRecord(g_evStep[c], 0);
            cudaStreamWaitEvent(g_s2, g_evStep[c], 0);
            k_dec<<<dim3(CHSTEP * 32 / 128, VV / 64), 256, DEC_SMEM, g_s2>>>(
                c * (CHSTEP * 32 / 128), dec_b, logits);
        }
    }

    // join: all decoder chunks must finish before the graph's end
    cudaEventRecord(g_evDec, g_s2);
    cudaStreamWaitEvent(0, g_evDec, 0);
}

// round 14
// speedup vs baseline: 1.0728x; 1.0611x over previous
#include <cuda_runtime.h>
#include <math.h>

#define SS 128
#define BB 32
#define VV 32000
#define NINP 1024
#define NHID 1024
#define NHEADS 16
#define HD 64
#define KSPLIT 8
#define CHSTEP 8   // decoder chunk = 8 steps = 256 rows

// ---------------- blobs: bf16 hi/lo pre-laid-out smem images ----------------
// Units: word = 32-bit; uint4 = 4 words. Weight chunk = [wh 64x36][wl 64x36] = 4608 words
// = 1152 uint4. X chunk = [xh 32x36][xl 32x36] = 2304 words = 576 uint4.
static __device__ uint4 g_wq[(size_t)16 * 16 * 1152];    // q_w cols 1024..2047   [1024][1024]
static __device__ uint4 g_wi[(size_t)64 * 48 * 1152];    // int_w cols [h|q|attn] [4096][3072]
static __device__ uint4 g_wf[(size_t)48 * 64 * 1152];    // fin_w                 [3072][4096]
static __device__ uint4 g_wd[(size_t)500 * 16 * 1152];   // dec_w                 [32000][1024]
static __device__ uint4 g_ximg[(size_t)48 * 576];        // chunks 0-15 h, 16-31 q, 32-47 attn
static __device__ uint4 g_iimg[(size_t)64 * 576];        // inter
// decoder A chunk image: [ah 128x36][al 128x36] = 9216 words = 2304 uint4
static __device__ uint4 g_aimg[(size_t)32 * 16 * 2304];
static __device__ float g_emb[(size_t)SS * BB * NINP];   // raw fp32 embeddings
static __device__ float g_kcache[(size_t)(SS + 1) * BB * NHID];
static __device__ float g_vcache[(size_t)(SS + 1) * BB * NHID];
static __device__ float g_part[KSPLIT * BB * 4096];
static __device__ float g_qpe[(size_t)SS * BB * 1024];   // e @ q_w[:, :1024].T
static __device__ float g_ipe[(size_t)SS * BB * 4096];   // e @ int_w[:, :1024].T

// ---------------- helpers ----------------
__device__ __forceinline__ unsigned packbf(float e, float o) {
    unsigned r;
    asm("cvt.rn.bf16x2.f32 %0, %1, %2;" : "=r"(r) : "f"(o), "f"(e));
    return r;
}
__device__ __forceinline__ void splitpair(float v0, float v1, unsigned& h, unsigned& l) {
    h = packbf(v0, v1);
    float r0 = v0 - __uint_as_float(h << 16);
    float r1 = v1 - __uint_as_float(h & 0xffff0000u);
    l = packbf(r0, r1);
}
__device__ __forceinline__ void cvtpair(float4 v, unsigned* ph, unsigned* pl) {
    unsigned h0 = packbf(v.x, v.y);
    unsigned h1 = packbf(v.z, v.w);
    float r0 = v.x - __uint_as_float(h0 << 16);
    float r1 = v.y - __uint_as_float(h0 & 0xffff0000u);
    float r2 = v.z - __uint_as_float(h1 << 16);
    float r3 = v.w - __uint_as_float(h1 & 0xffff0000u);
    ph[0] = h0; ph[1] = h1;
    pl[0] = packbf(r0, r1);
    pl[1] = packbf(r2, r3);
}
__device__ __forceinline__ void mmabf(float* c, unsigned a0, unsigned a1, unsigned a2,
                                      unsigned a3, unsigned b0, unsigned b1) {
    asm volatile(
        "mma.sync.aligned.m16n8k16.row.col.f32.bf16.bf16.f32 "
        "{%0,%1,%2,%3},{%4,%5,%6,%7},{%8,%9},{%0,%1,%2,%3};"
        : "+f"(c[0]), "+f"(c[1]), "+f"(c[2]), "+f"(c[3])
        : "r"(a0), "r"(a1), "r"(a2), "r"(a3), "r"(b0), "r"(b1));
}
__device__ __forceinline__ void cp_commit() { asm volatile("cp.async.commit_group;"); }
template <int N>
__device__ __forceinline__ void cp_wait() { asm volatile("cp.async.wait_group %0;" ::"n"(N)); }
#define CPA16(d, s) asm volatile("cp.async.cg.shared.global [%0], [%1], 16;" ::"r"(d), "l"(s))

// ---------------- one-time weight conversion into blob layout ----------------
// permute 0: src col = k; permute 1 (int): src col = (k<1024) ? k+3072 : k
__global__ void k_cvt_w(const float* __restrict__ src, unsigned* __restrict__ dst,
                        int N, int Kdst, int ldsrc, int permute) {
    long total = (long)N * (Kdst >> 1);
    long stride = (long)gridDim.x * blockDim.x;
    int KC = Kdst >> 6;
    for (long i = (long)blockIdx.x * blockDim.x + threadIdx.x; i < total; i += stride) {
        int n = (int)(i / (Kdst >> 1));
        int kw = (int)(i - (long)n * (Kdst >> 1));
        int k = 2 * kw;
        int kk = permute ? ((k < 1024) ? k + 3072 : k) : k;
        float2 v = *(const float2*)(src + (size_t)n * ldsrc + kk);
        unsigned h, l;
        splitpair(v.x, v.y, h, l);
        int nt = n >> 6, r = n & 63, gc = kw >> 5, w = kw & 31;
        size_t base = ((size_t)nt * KC + gc) * 4608;   // words
        dst[base + r * 36 + w] = h;
        dst[base + 2304 + r * 36 + w] = l;
    }
}

// ---------------- setup ----------------
__global__ void k_embed(const int* __restrict__ obs, const float* __restrict__ enc_w) {
    int idx = blockIdx.x;  // s*B + b
    int row = obs[idx];
    ((float4*)(g_emb + (size_t)idx * NINP))[threadIdx.x] =
        ((const float4*)(enc_w + (size_t)row * NINP))[threadIdx.x];
}

__global__ void k_init(const float* __restrict__ h0v, const float* __restrict__ kc0,
                       const float* __restrict__ vc0, float* __restrict__ states_full) {
    int b = blockIdx.x, t = threadIdx.x;
    float4 h = ((const float4*)(h0v + b * NHID))[t];
    unsigned h0, l0, h1, l1;
    splitpair(h.x, h.y, h0, l0);
    splitpair(h.z, h.w, h1, l1);
    int d = 4 * t;   // hidden -> ximg chunks 0-15
    unsigned* x = (unsigned*)g_ximg + ((size_t)(d >> 6)) * 2304 + b * 36 + ((d & 63) >> 1);
    x[0] = h0; x[1] = h1;
    x[1152] = l0; x[1153] = l1;
    ((float4*)(states_full + (size_t)b * NHID))[t] = h;
    ((float4*)(g_kcache + (size_t)b * NHID))[t] = ((const float4*)(kc0 + b * NHID))[t];
    ((float4*)(g_vcache + (size_t)b * NHID))[t] = ((const float4*)(vc0 + b * NHID))[t];
}

// ---------------- step GEMM: cp.async blobs -> smem (round-10 verbatim body) ----------
__global__ __launch_bounds__(256, 4) void k_gemm(const uint4* __restrict__ xbase,
                                                 const uint4* __restrict__ wblob,
                                                 int KC, int CH, int N) {
    extern __shared__ uint4 dsm[];
    unsigned sb = (unsigned)__cvta_generic_to_shared(dsm);
    const int tid = threadIdx.x;
    const int nt = blockIdx.x, kidx = blockIdx.y;
    const int w = tid >> 5, lane = tid & 31, g = lane >> 2, tig = lane & 3;
    float acc[2][4] = {};

    auto issue = [&](int stage, int cc) {
        int gc = kidx * CH + cc;
        const uint4* wsrc = wblob + ((size_t)nt * KC + gc) * 1152;
        const uint4* xsrc = xbase + (size_t)gc * 576;
        unsigned db = sb + stage * 27648;
        for (int u = tid; u < 1728; u += 256) {
            const uint4* s_ = (u < 576) ? (xsrc + u) : (wsrc + (u - 576));
            CPA16(db + u * 16, s_);
        }
        cp_commit();
    };

    issue(0, 0);
    issue(1, 1);
    for (int cc = 0; cc < CH; cc++) {
        cp_wait<1>();
        __syncthreads();
        const unsigned* st = (const unsigned*)dsm + (cc & 1) * 6912;
        const unsigned* xh = st;
        const unsigned* xl = st + 1152;
        const unsigned* wh = st + 2304;
        const unsigned* wl = st + 4608;
#pragma unroll
        for (int s = 0; s < 4; s++) {
            int w0 = s * 8 + tig, w1 = w0 + 4;
            unsigned bh0 = wh[(w * 8 + g) * 36 + w0], bh1 = wh[(w * 8 + g) * 36 + w1];
            unsigned bl0 = wl[(w * 8 + g) * 36 + w0], bl1 = wl[(w * 8 + g) * 36 + w1];
#pragma unroll
            for (int mt = 0; mt < 2; mt++) {
                int r0 = mt * 16 + g;
                unsigned ah0 = xh[r0 * 36 + w0], ah1 = xh[(r0 + 8) * 36 + w0];
                unsigned ah2 = xh[r0 * 36 + w1], ah3 = xh[(r0 + 8) * 36 + w1];
                unsigned al0 = xl[r0 * 36 + w0], al1 = xl[(r0 + 8) * 36 + w0];
                unsigned al2 = xl[r0 * 36 + w1], al3 = xl[(r0 + 8) * 36 + w1];
                mmabf(acc[mt], ah0, ah1, ah2, ah3, bh0, bh1);
                mmabf(acc[mt], ah0, ah1, ah2, ah3, bl0, bl1);
                mmabf(acc[mt], al0, al1, al2, al3, bh0, bh1);
            }
        }
        __syncthreads();
        if (cc + 2 < CH) issue(cc & 1, cc + 2);
        else cp_commit();
    }
    float* p = g_part + (size_t)kidx * 32 * N;
    int n0 = nt * 64 + w * 8 + 2 * tig;
#pragma unroll
    for (int mt = 0; mt < 2; mt++) {
        int r0 = mt * 16 + g;
        *(float2*)&p[r0 * N + n0] = make_float2(acc[mt][0], acc[mt][1]);
        *(float2*)&p[(r0 + 8) * N + n0] = make_float2(acc[mt][2], acc[mt][3]);
    }
}

// ---------------- fused LN(q)+relu + attention (r10 + qpe partial; q->ximg 16-31) -------
__global__ __launch_bounds__(512) void k_lnq_attn(const float* __restrict__ qb,
                                                  const float* __restrict__ gg,
                                                  const float* __restrict__ bbv, int step) {
    __shared__ float q[1024];
    __shared__ float sc[NHEADS][132];
    __shared__ float r1[16], r2[16];
    int b = blockIdx.x, tid = threadIdx.x, lane = tid & 31, wid = tid >> 5;

    float2 v = *(const float2*)(qb + 2 * tid);
    {
        float2 pe = *(const float2*)(g_qpe + ((size_t)step * BB + b) * 1024 + 2 * tid);
        v.x += pe.x; v.y += pe.y;
    }
#pragma unroll
    for (int j = 0; j < KSPLIT; j++) {
        float2 p = *(const float2*)(g_part + (size_t)j * 32 * 1024 + b * 1024 + 2 * tid);
        v.x += p.x; v.y += p.y;
    }
    float s1 = v.x + v.y, s2 = v.x * v.x + v.y * v.y;
#pragma unroll
    for (int o = 16; o; o >>= 1) {
        s1 += __shfl_xor_sync(0xffffffffu, s1, o);
        s2 += __shfl_xor_sync(0xffffffffu, s2, o);
    }
    if (lane == 0) { r1[wid] = s1; r2[wid] = s2; }
    __syncthreads();
    s1 = 0.f; s2 = 0.f;
#pragma unroll
    for (int i = 0; i < 16; i++) { s1 += r1[i]; s2 += r2[i]; }
    float mu = s1 * (1.f / 1024.f);
    float rstd = rsqrtf(s2 * (1.f / 1024.f) - mu * mu + 1e-5f);
    float q0 = fmaxf((v.x - mu) * rstd * gg[2 * tid] + bbv[2 * tid], 0.f);
    float q1 = fmaxf((v.y - mu) * rstd * gg[2 * tid + 1] + bbv[2 * tid + 1], 0.f);
    q[2 * tid] = q0;
    q[2 * tid + 1] = q1;
    {
        unsigned h_, l_;
        splitpair(q0, q1, h_, l_);
        unsigned* x = (unsigned*)g_ximg + ((size_t)(16 + (tid >> 5))) * 2304 + b * 36 + (tid & 31);
        x[0] = h_;
        x[1152] = l_;
    }
    __syncthreads();

    const int hh = wid;
    const int L = step + 1;
    const float* qh = q + hh * HD;
    float msc[4], m = -1e30f;
#pragma unroll
    for (int i = 0; i < 4; i++) {
        int c = lane + i * 32;
        float d = -1e30f;
        if (c < L) {
            const float* kr = g_kcache + ((size_t)c * BB + b) * NHID + hh * HD;
            float acc = 0.f;
#pragma unroll
            for (int j = 0; j < 16; j++) {
                float4 kv = *(const float4*)&kr[j * 4];
                acc += qh[j * 4] * kv.x + qh[j * 4 + 1] * kv.y +
                       qh[j * 4 + 2] * kv.z + qh[j * 4 + 3] * kv.w;
            }
            d = acc * 0.125f;
        }
        msc[i] = d;
        m = fmaxf(m, d);
    }
#pragma unroll
    for (int o = 16; o; o >>= 1) m = fmaxf(m, __shfl_xor_sync(0xffffffffu, m, o));
    float se = 0.f;
#pragma unroll
    for (int i = 0; i < 4; i++) {
        float e = expf(msc[i] - m);
        sc[hh][lane + i * 32] = e;
        se += e;
    }
#pragma unroll
    for (int o = 16; o; o >>= 1) se += __shfl_xor_sync(0xffffffffu, se, o);
    float inv = 1.f / se;
    __syncwarp();

    float o0 = 0.f, o1 = 0.f;
    const float* vbase = g_vcache + (size_t)b * NHID + hh * HD + 2 * lane;
#pragma unroll 4
    for (int c = 0; c < L; c++) {
        float wgt = sc[hh][c];
        float2 vv = *(const float2*)(vbase + (size_t)c * BB * NHID);
        o0 += wgt * vv.x;
        o1 += wgt * vv.y;
    }
    o0 *= inv; o1 *= inv;
    unsigned oh, ol;
    splitpair(o0, o1, oh, ol);
    unsigned* x = (unsigned*)g_ximg + ((size_t)(32 + hh)) * 2304 + b * 36 + lane;
    x[0] = oh;
    x[1152] = ol;
}

// ---------------- LN(int)+relu -> iimg (r10 + ipe partial) ----------------
__global__ __launch_bounds__(256) void k_ln_int(const float* __restrict__ bias,
                                                const float* __restrict__ gg,
                                                const float* __restrict__ bb2, int step) {
    __shared__ float pre[4096];
    __shared__ float red1[8], red2[8];
    int b = blockIdx.x, tid = threadIdx.x, lane = tid & 31, wid = tid >> 5;
    float s1 = 0.f, s2 = 0.f;
#pragma unroll
    for (int i = 0; i < 4; i++) {
        int c = (tid + i * 256) * 4;
        float4 v = *(const float4*)&bias[c];
        {
            float4 pe = *(const float4*)(g_ipe + ((size_t)step * BB + b) * 4096 + c);
            v.x += pe.x; v.y += pe.y; v.z += pe.z; v.w += pe.w;
        }
#pragma unroll
        for (int j = 0; j < KSPLIT; j++) {
            float4 p = *(const float4*)&g_part[(size_t)j * 32 * 4096 + b * 4096 + c];
            v.x += p.x; v.y += p.y; v.z += p.z; v.w += p.w;
        }
        *(float4*)&pre[c] = v;
        s1 += v.x + v.y + v.z + v.w;
        s2 += v.x * v.x + v.y * v.y + v.z * v.z + v.w * v.w;
    }
#pragma unroll
    for (int o = 16; o; o >>= 1) {
        s1 += __shfl_xor_sync(0xffffffffu, s1, o);
        s2 += __shfl_xor_sync(0xffffffffu, s2, o);
    }
    if (lane == 0) { red1[wid] = s1; red2[wid] = s2; }
    __syncthreads();
    s1 = 0.f; s2 = 0.f;
#pragma unroll
    for (int i = 0; i < 8; i++) { s1 += red1[i]; s2 += red2[i]; }
    float mu = s1 * (1.f / 4096.f);
    float rstd = rsqrtf(s2 * (1.f / 4096.f) - mu * mu + 1e-5f);
#pragma unroll
    for (int i = 0; i < 8; i++) {
        int c2 = 2 * (tid + i * 256);
        float y0 = fmaxf((pre[c2] - mu) * rstd * gg[c2] + bb2[c2], 0.f);
        float y1 = fmaxf((pre[c2 + 1] - mu) * rstd * gg[c2 + 1] + bb2[c2 + 1], 0.f);
        unsigned h_, l_;
        splitpair(y0, y1, h_, l_);
        unsigned* o = (unsigned*)g_iimg + ((size_t)(c2 >> 6)) * 2304 + b * 36 + ((c2 & 63) >> 1);
        o[0] = h_;
        o[1152] = l_;
    }
}

// ---------------- LN(fin)+relu -> caches/states + ximg hidden + decoder-A blob -----------
__global__ __launch_bounds__(256) void k_ln_fin(const float* __restrict__ bias,
                                                const float* __restrict__ gg,
                                                const float* __restrict__ bb2, int step,
                                                float* __restrict__ states_full) {
    __shared__ float pre[3072];
    __shared__ float red1[8], red2[8];
    int b = blockIdx.x, tid = threadIdx.x, lane = tid & 31, wid = tid >> 5;
    float s1 = 0.f, s2 = 0.f;
#pragma unroll
    for (int i = 0; i < 3; i++) {
        int c = (tid + i * 256) * 4;
        float4 v = *(const float4*)&bias[c];
#pragma unroll
        for (int j = 0; j < KSPLIT; j++) {
            float4 p = *(const float4*)&g_part[(size_t)j * 32 * 3072 + b * 3072 + c];
            v.x += p.x; v.y += p.y; v.z += p.z; v.w += p.w;
        }
        *(float4*)&pre[c] = v;
        s1 += v.x + v.y + v.z + v.w;
        s2 += v.x * v.x + v.y * v.y + v.z * v.z + v.w * v.w;
    }
#pragma unroll
    for (int o = 16; o; o >>= 1) {
        s1 += __shfl_xor_sync(0xffffffffu, s1, o);
        s2 += __shfl_xor_sync(0xffffffffu, s2, o);
    }
    if (lane == 0) { red1[wid] = s1; red2[wid] = s2; }
    __syncthreads();
    s1 = 0.f; s2 = 0.f;
#pragma unroll
    for (int i = 0; i < 8; i++) { s1 += red1[i]; s2 += red2[i]; }
    float mu = s1 * (1.f / 3072.f);
    float rstd = rsqrtf(s2 * (1.f / 3072.f) - mu * mu + 1e-5f);
#pragma unroll
    for (int i = 0; i < 6; i++) {
        int c2 = 2 * (tid + i * 256);
        float y0 = fmaxf((pre[c2] - mu) * rstd * gg[c2] + bb2[c2], 0.f);
        float y1 = fmaxf((pre[c2 + 1] - mu) * rstd * gg[c2 + 1] + bb2[c2 + 1], 0.f);
        if (c2 < 1024) {
            *(float2*)&g_kcache[((size_t)(step + 1) * BB + b) * NHID + c2] = make_float2(y0, y1);
        } else if (c2 < 2048) {
            *(float2*)&g_vcache[((size_t)(step + 1) * BB + b) * NHID + (c2 - 1024)] =
                make_float2(y0, y1);
        } else {
            int d = c2 - 2048;
            *(float2*)&states_full[((size_t)(step + 1) * BB + b) * NHID + d] = make_float2(y0, y1);
            unsigned h_, l_;
            splitpair(y0, y1, h_, l_);
            unsigned* x = (unsigned*)g_ximg + ((size_t)(d >> 6)) * 2304 + b * 36 + ((d & 63) >> 1);
            x[0] = h_;
            x[1152] = l_;
            int ar = step * 32 + b;
            unsigned* a = (unsigned*)g_aimg + ((size_t)((ar >> 7) * 16 + (d >> 6))) * 9216 +
                          (ar & 127) * 36 + ((d & 63) >> 1);
            a[0] = h_;
            a[4608] = l_;
        }
    }
}

// ---------------- decoder chunk: 128m x 64n tiles, cp.async blobs ----------------
__global__ __launch_bounds__(256, 2) void k_dec(int mb0, const float* __restrict__ bias,
                                                float* __restrict__ out) {
    extern __shared__ uint4 dsm[];
    unsigned sb = (unsigned)__cvta_generic_to_shared(dsm);
    const int tid = threadIdx.x;
    const int mb = mb0 + blockIdx.x, nbk = blockIdx.y;
    const int w = tid >> 5, lane = tid & 31, g = lane >> 2, tig = lane & 3;
    const int mw = w >> 1, nw = w & 1;
    float acc[2][4][4] = {};

    auto issue = [&](int stage, int gc) {
        const uint4* asrc = g_aimg + ((size_t)(mb * 16 + gc)) * 2304;
        const uint4* wsrc = g_wd + ((size_t)(nbk * 16 + gc)) * 1152;
        unsigned db = sb + stage * 55296;
        for (int u = tid; u < 3456; u += 256) {
            const uint4* s_ = (u < 2304) ? (asrc + u) : (wsrc + (u - 2304));
            CPA16(db + u * 16, s_);
        }
        cp_commit();
    };

    issue(0, 0);
    issue(1, 1);
    for (int cc = 0; cc < 16; cc++) {
        cp_wait<1>();
        __syncthreads();
        const unsigned* st = (const unsigned*)dsm + (cc & 1) * 13824;
        const unsigned* ah = st;
        const unsigned* al = st + 4608;
        const unsigned* wh = st + 9216;
        const unsigned* wl = st + 11520;
#pragma unroll
        for (int s = 0; s < 4; s++) {
            int w0 = s * 8 + tig, w1 = w0 + 4;
            unsigned bh[4][2], bl[4][2];
#pragma unroll
            for (int nt = 0; nt < 4; nt++) {
                int col = nw * 32 + nt * 8 + g;
                bh[nt][0] = wh[col * 36 + w0];
                bh[nt][1] = wh[col * 36 + w1];
                bl[nt][0] = wl[col * 36 + w0];
                bl[nt][1] = wl[col * 36 + w1];
            }
#pragma unroll
            for (int mt = 0; mt < 2; mt++) {
                int r0 = mw * 32 + mt * 16 + g;
                unsigned a0 = ah[r0 * 36 + w0], a1 = ah[(r0 + 8) * 36 + w0];
                unsigned a2 = ah[r0 * 36 + w1], a3 = ah[(r0 + 8) * 36 + w1];
                unsigned l0 = al[r0 * 36 + w0], l1 = al[(r0 + 8) * 36 + w0];
                unsigned l2 = al[r0 * 36 + w1], l3 = al[(r0 + 8) * 36 + w1];
#pragma unroll
                for (int nt = 0; nt < 4; nt++) {
                    mmabf(acc[mt][nt], a0, a1, a2, a3, bh[nt][0], bh[nt][1]);
                    mmabf(acc[mt][nt], a0, a1, a2, a3, bl[nt][0], bl[nt][1]);
                    mmabf(acc[mt][nt], l0, l1, l2, l3, bh[nt][0], bh[nt][1]);
                }
            }
        }
        __syncthreads();
        if (cc + 2 < 16) issue(cc & 1, cc + 2);
        else cp_commit();
    }
#pragma unroll
    for (int mt = 0; mt < 2; mt++) {
        int r0g = mb * 128 + mw * 32 + mt * 16 + g;
#pragma unroll
        for (int nt = 0; nt < 4; nt++) {
            int c0 = nbk * 64 + nw * 32 + nt * 8 + 2 * tig;
            float2 bv = *(const float2*)&bias[c0];
            *(float2*)&out[(size_t)r0g * VV + c0] =
                make_float2(acc[mt][nt][0] + bv.x, acc[mt][nt][1] + bv.y);
            *(float2*)&out[(size_t)(r0g + 8) * VV + c0] =
                make_float2(acc[mt][nt][2] + bv.x, acc[mt][nt][3] + bv.y);
        }
    }
}

// ---------------- big GEMM for precomputes: out = A @ W.T ----------------
__global__ __launch_bounds__(256, 1) void k_bigemm(const float* __restrict__ A,
                                                   const float* __restrict__ Wd, int ldw,
                                                   float* __restrict__ out, long ldo) {
    __shared__ unsigned ah[128][20], al[128][20], bh_[128][20], bl_[128][20];
    int tid = threadIdx.x;
    int mb = blockIdx.x * 128, nb = blockIdx.y * 128;
    int w = tid >> 5, lane = tid & 31, g = lane >> 2, tig = lane & 3;
    int mw = w >> 2, nw = w & 3;
    float acc[4][4][4] = {};
    float4 aa[4], wv[4];

    auto load = [&](int kc) {
#pragma unroll
        for (int i = 0; i < 4; i++) {
            int e = tid + i * 256;
            int r = e >> 3, cg = (e & 7) << 2;
            aa[i] = *(const float4*)(A + (size_t)(mb + r) * 1024 + kc + cg);
            wv[i] = *(const float4*)(Wd + (size_t)(nb + r) * ldw + kc + cg);
        }
    };
    auto store = [&]() {
#pragma unroll
        for (int i = 0; i < 4; i++) {
            int e = tid + i * 256;
            int r = e >> 3, wd = (e & 7) * 2;
            cvtpair(aa[i], &ah[r][wd], &al[r][wd]);
            cvtpair(wv[i], &bh_[r][wd], &bl_[r][wd]);
        }
    };

    load(0);
    for (int c = 0; c < 32; c++) {
        store();
        __syncthreads();
        if (c < 31) load((c + 1) * 32);
#pragma unroll
        for (int s = 0; s < 2; s++) {
            int w0 = s * 8 + tig, w1 = w0 + 4;
            unsigned bh[4][2], bl[4][2];
#pragma unroll
            for (int nt = 0; nt < 4; nt++) {
                int col = nw * 32 + nt * 8 + g;
                bh[nt][0] = bh_[col][w0]; bh[nt][1] = bh_[col][w1];
                bl[nt][0] = bl_[col][w0]; bl[nt][1] = bl_[col][w1];
            }
#pragma unroll
            for (int mt = 0; mt < 4; mt++) {
                int r0 = mw * 64 + mt * 16 + g;
                unsigned a0 = ah[r0][w0], a1 = ah[r0 + 8][w0], a2 = ah[r0][w1], a3 = ah[r0 + 8][w1];
                unsigned l0 = al[r0][w0], l1 = al[r0 + 8][w0], l2 = al[r0][w1], l3 = al[r0 + 8][w1];
#pragma unroll
                for (int nt = 0; nt < 4; nt++) {
                    mmabf(acc[mt][nt], a0, a1, a2, a3, bh[nt][0], bh[nt][1]);
                    mmabf(acc[mt][nt], a0, a1, a2, a3, bl[nt][0], bl[nt][1]);
                    mmabf(acc[mt][nt], l0, l1, l2, l3, bh[nt][0], bh[nt][1]);
                }
            }
        }
        __syncthreads();
    }
#pragma unroll
    for (int mt = 0; mt < 4; mt++) {
        int r0 = mb + mw * 64 + mt * 16 + g;
#pragma unroll
        for (int nt = 0; nt < 4; nt++) {
            int c0 = nb + nw * 32 + nt * 8 + 2 * tig;
            *(float2*)&out[(size_t)r0 * ldo + c0] = make_float2(acc[mt][nt][0], acc[mt][nt][1]);
            *(float2*)&out[(size_t)(r0 + 8) * ldo + c0] = make_float2(acc[mt][nt][2], acc[mt][nt][3]);
        }
    }
}

// ---------------- launch ----------------
static cudaStream_t g_s2 = nullptr;
static cudaEvent_t g_evFork, g_evPre, g_evDec, g_evStep[SS / CHSTEP];

extern "C" void kernel_launch(void* const* d_in, const int* in_sizes, int n_in,
                              void* d_out, int out_size) {
    (void)in_sizes; (void)n_in; (void)out_size;
    const int* obs = (const int*)d_in[0];
    const float* hidden_init = (const float*)d_in[1];
    const float* kinit = (const float*)d_in[2];
    const float* vinit = (const float*)d_in[3];
    const float* enc_w = (const float*)d_in[4];
    const float* q_w = (const float*)d_in[5];
    const float* q_b = (const float*)d_in[6];
    const float* qn_g = (const float*)d_in[7];
    const float* qn_b = (const float*)d_in[8];
    const float* int_w = (const float*)d_in[9];
    const float* int_b = (const float*)d_in[10];
    const float* intn_g = (const float*)d_in[11];
    const float* intn_b = (const float*)d_in[12];
    const float* fin_w = (const float*)d_in[13];
    const float* fin_b = (const float*)d_in[14];
    const float* fn_g = (const float*)d_in[15];
    const float* fn_b = (const float*)d_in[16];
    const float* dec_w = (const float*)d_in[17];
    const float* dec_b = (const float*)d_in[18];

    float* logits = (float*)d_out;
    float* states_full = logits + (size_t)SS * BB * VV;

    if (!g_s2) {
        int lo = 0, hi = 0;
        cudaDeviceGetStreamPriorityRange(&lo, &hi);
        if (cudaStreamCreateWithPriority(&g_s2, cudaStreamNonBlocking, lo) != cudaSuccess)
            cudaStreamCreateWithFlags(&g_s2, cudaStreamNonBlocking);
        cudaEventCreateWithFlags(&g_evFork, cudaEventDisableTiming);
        cudaEventCreateWithFlags(&g_evPre, cudaEventDisableTiming);
        cudaEventCreateWithFlags(&g_evDec, cudaEventDisableTiming);
        for (int i = 0; i < SS / CHSTEP; i++)
            cudaEventCreateWithFlags(&g_evStep[i], cudaEventDisableTiming);
    }

    const int GEMM_SMEM = 2 * 27648;   // 55296 B
    const int DEC_SMEM = 2 * 55296;    // 110592 B
    cudaFuncSetAttribute(k_gemm, cudaFuncAttributeMaxDynamicSharedMemorySize, GEMM_SMEM);
    cudaFuncSetAttribute(k_dec, cudaFuncAttributeMaxDynamicSharedMemorySize, DEC_SMEM);

    unsigned *wq, *wi, *wf, *wd;
    cudaGetSymbolAddress((void**)&wq, g_wq);
    cudaGetSymbolAddress((void**)&wi, g_wi);
    cudaGetSymbolAddress((void**)&wf, g_wf);
    cudaGetSymbolAddress((void**)&wd, g_wd);
    uint4 *bq, *bi, *bf, *bx, *bii;
    cudaGetSymbolAddress((void**)&bq, g_wq);
    cudaGetSymbolAddress((void**)&bi, g_wi);
    cudaGetSymbolAddress((void**)&bf, g_wf);
    cudaGetSymbolAddress((void**)&bx, g_ximg);
    cudaGetSymbolAddress((void**)&bii, g_iimg);
    float *qpe, *ipe, *embp;
    cudaGetSymbolAddress((void**)&qpe, g_qpe);
    cudaGetSymbolAddress((void**)&ipe, g_ipe);
    cudaGetSymbolAddress((void**)&embp, g_emb);

    k_embed<<<SS * BB, 256>>>(obs, enc_w);
    k_init<<<BB, 256>>>(hidden_init, kinit, vinit, states_full);

    // fork side stream: wq blob + qpe (needed at step 0) then wd blob (needed at step 7)
    cudaEventRecord(g_evFork, 0);
    cudaStreamWaitEvent(g_s2, g_evFork, 0);
    k_cvt_w<<<2048, 256, 0, g_s2>>>(q_w, wq, 1024, 1024, 2048, 0);          // cols 1024.. via permute 0 on q_w+1024
    // NOTE: wq must come from q_w cols 1024..2047:
    k_cvt_w<<<2048, 256, 0, g_s2>>>(q_w + 1024, wq, 1024, 1024, 2048, 0);
    k_bigemm<<<dim3(32, 8), 256, 0, g_s2>>>(embp, q_w, 2048, qpe, 1024);
    cudaEventRecord(g_evPre, g_s2);
    k_cvt_w<<<8192, 256, 0, g_s2>>>(dec_w, wd, 32000, 1024, 1024, 0);
    // main stream: wi/wf blobs + ipe
    k_cvt_w<<<4096, 256>>>(int_w, wi, 4096, 3072, 4096, 1);
    k_cvt_w<<<4096, 256>>>(fin_w, wf, 3072, 4096, 4096, 0);
    k_bigemm<<<dim3(32, 32), 256>>>(embp, int_w, 4096, ipe, 4096);
    cudaStreamWaitEvent(0, g_evPre, 0);

    for (int s = 0; s < SS; s++) {
        // q partial (hidden half; e-half precomputed): 16 chunks over ximg 0-15
        k_gemm<<<dim3(16, KSPLIT), 256, GEMM_SMEM>>>(bx, bq, 16, 2, 1024);
        k_lnq_attn<<<BB, 512>>>(q_b, qn_g, qn_b, s);
        // int partial over x=[h|q|attn]: 48 chunks
        k_gemm<<<dim3(64, KSPLIT), 256, GEMM_SMEM>>>(bx, bi, 48, 6, 4096);
        k_ln_int<<<BB, 256>>>(int_b, intn_g, intn_b, s);
        // fin over inter: 64 chunks
        k_gemm<<<dim3(48, KSPLIT), 256, GEMM_SMEM>>>(bii, bf, 64, 8, 3072);
        k_ln_fin<<<BB, 256>>>(fin_b, fn_g, fn_b, s, states_full);

        if ((s & (CHSTEP - 1)) == (CHSTEP - 1)) {
            int c = s / CHSTEP;
            cudaEventRecord(g_evStep[c], 0);
            cudaStreamWaitEvent(g_s2, g_evStep[c], 0);
            k_dec<<<dim3(CHSTEP * 32 / 128, VV / 64), 256, DEC_SMEM, g_s2>>>(
                c * (CHSTEP * 32 / 128), dec_b, logits);
        }
    }

    cudaEventRecord(g_evDec, g_s2);
    cudaStreamWaitEvent(0, g_evDec, 0);
}